// round 11
// baseline (speedup 1.0000x reference)
#include <cuda_runtime.h>
#include <cuda_bf16.h>
#include <cstdint>
#include <math.h>

typedef __nv_bfloat16 bf;

// Problem constants
#define BB 4
#define SS 2048
#define HH 1024
#define RR 512
#define NHEAD 8
#define HDIM 64
#define NTOK 8192L   // B*S

// ===========================================================================
// Baseline-PTX helpers (sm_80-era: ldmatrix / mma.sync / cp.async)
// ===========================================================================
__device__ __forceinline__ uint32_t smem_to_u32(const void* p) {
    uint32_t a;
    asm("{ .reg .u64 t; cvta.to.shared.u64 t, %1; cvt.u32.u64 %0, t; }" : "=r"(a) : "l"(p));
    return a;
}
__device__ __forceinline__ void ldm_x4(uint32_t* r, uint32_t addr) {
    asm volatile("ldmatrix.sync.aligned.m8n8.x4.shared.b16 {%0,%1,%2,%3}, [%4];"
                 : "=r"(r[0]), "=r"(r[1]), "=r"(r[2]), "=r"(r[3]) : "r"(addr));
}
__device__ __forceinline__ void mma_bf16(float* d, const uint32_t* a, const uint32_t* b) {
    asm volatile("mma.sync.aligned.m16n8k16.row.col.f32.bf16.bf16.f32 "
                 "{%0,%1,%2,%3}, {%4,%5,%6,%7}, {%8,%9}, {%0,%1,%2,%3};"
                 : "+f"(d[0]), "+f"(d[1]), "+f"(d[2]), "+f"(d[3])
                 : "r"(a[0]), "r"(a[1]), "r"(a[2]), "r"(a[3]), "r"(b[0]), "r"(b[1]));
}
#define CP_ASYNC16(dst, src) \
    asm volatile("cp.async.cg.shared.global [%0], [%1], 16;" :: "r"(dst), "l"(src))
#define CP_COMMIT() asm volatile("cp.async.commit_group;" ::: "memory")
#define CP_WAIT1()  asm volatile("cp.async.wait_group 1;" ::: "memory")
#define CP_WAIT0()  asm volatile("cp.async.wait_group 0;" ::: "memory")

// Swizzled smem offset: rows of 64B (32 bf16), 4x 16B chunks, XOR by (row>>1)&3
#define SWZ(row, c) ((uint32_t)((row) * 64 + (((c) ^ (((row) >> 1) & 3)) << 4)))

// ===========================================================================
// Scratch (static device globals; no allocation allowed)
// ===========================================================================
__device__ float d_pooled[BB * HH];
__device__ float d_r[NTOK * RR];
__device__ float d_tmpf[NTOK * HH];
__device__ float d_reason[NTOK * HH];

__device__ bf d_cat_h[NTOK * 2 * HH], d_cat_l[NTOK * 2 * HH];   // [hs | reasoned]
__device__ bf d_y_h[NTOK * RR],   d_y_l[NTOK * RR];
__device__ bf d_qkv_h[NTOK * 3 * RR], d_qkv_l[NTOK * 3 * RR];
__device__ bf d_vt_h[(long)BB * NHEAD * HDIM * SS], d_vt_l[(long)BB * NHEAD * HDIM * SS];
__device__ bf d_o_h[NTOK * RR],   d_o_l[NTOK * RR];
__device__ bf d_ff_h[NTOK * 4 * RR], d_ff_l[NTOK * 4 * RR];
__device__ bf d_rs_h[NTOK * RR],  d_rs_l[NTOK * RR];
__device__ bf d_t2_h[NTOK * HH],  d_t2_l[NTOK * HH];
// transposed + split weights ([N,K] bf16)
__device__ bf d_rpT_h[RR * HH],       d_rpT_l[RR * HH];
__device__ bf d_qkvT_h[3 * RR * RR],  d_qkvT_l[3 * RR * RR];
__device__ bf d_woT_h[RR * RR],       d_woT_l[RR * RR];
__device__ bf d_ff1T_h[4 * RR * RR],  d_ff1T_l[4 * RR * RR];
__device__ bf d_ff2T_h[RR * 4 * RR],  d_ff2T_l[RR * 4 * RR];
__device__ bf d_opT_h[HH * RR],       d_opT_l[HH * RR];
__device__ bf d_g1T_h[HH * 2 * HH],   d_g1T_l[HH * 2 * HH];
__device__ bf d_g2T_h[HH * HH],       d_g2T_l[HH * HH];

// ===========================================================================
// Warp-MMA split-bf16 GEMM: D = Ah*Bh + Ah*Bl + Al*Bh (fp32 accum, HMMA)
//   A: [M,K] bf16 (K-major), B: [N,K] bf16 (K-major)
//   CTA tile 256 x 128, BK=32, 8 warps (4m x 2n), warp tile 64 x 64.
//   3-stage cp.async pipeline, single __syncthreads per chunk.
//   act: 0 none, 1 relu, 2 sigmoid, 3 fused gate: C = f1 + sigmoid(v)*f2
// ===========================================================================
__global__ void __launch_bounds__(256) gemm_tc_kernel(
    const bf* __restrict__ Ah, const bf* __restrict__ Al,
    const bf* __restrict__ Bh, const bf* __restrict__ Bl,
    const float* __restrict__ bias, const float* __restrict__ res,
    const float* __restrict__ f1, const float* __restrict__ f2,
    float* __restrict__ C, bf* __restrict__ Ch, bf* __restrict__ Cl,
    int K, int lda, int ldb, int ldc,
    long sAo, long sAi, long sBo, long sBi, long sCo, long sCi, int zdiv,
    float alpha, int act)
{
    constexpr int BM = 256, BN = 128;
    constexpr int ATB = BM * 64;                  // 16384 B per A matrix per stage
    constexpr int BTB = BN * 64;                  // 8192 B per B matrix per stage
    constexpr int STG = 2 * ATB + 2 * BTB;        // 49152 B per stage

    extern __shared__ char smem[];
    uint32_t sb = smem_to_u32(smem);

    int tid = threadIdx.x, wid = tid >> 5, lane = tid & 31;
    int wm = wid >> 1, wn = wid & 1;              // 4 x 2 warp grid

    long zb = blockIdx.z / zdiv, zi = blockIdx.z % zdiv;
    int m0 = blockIdx.y * BM, n0 = blockIdx.x * BN;
    const bf* gAh = Ah + zb * sAo + zi * sAi + (long)m0 * lda;
    const bf* gAl = Al + zb * sAo + zi * sAi + (long)m0 * lda;
    const bf* gBh = Bh + zb * sBo + zi * sBi + (long)n0 * ldb;
    const bf* gBl = Bl + zb * sBo + zi * sBi + (long)n0 * ldb;

    const int nc = K >> 5;   // 32-wide K chunks

    auto load_chunk = [&](int c, int s) {
        uint32_t base = sb + s * STG;
        long ko = (long)c << 5;
#pragma unroll
        for (int i = tid; i < 1024; i += 256) {          // A: 256 rows x 4 chunks
            int r = i >> 2, q = i & 3;
            long go = (long)r * lda + ko + q * 8;
            uint32_t so = SWZ(r, q);
            CP_ASYNC16(base + so,       gAh + go);
            CP_ASYNC16(base + ATB + so, gAl + go);
        }
#pragma unroll
        for (int i = tid; i < 512; i += 256) {           // B: 128 rows x 4 chunks
            int r = i >> 2, q = i & 3;
            long go = (long)r * ldb + ko + q * 8;
            uint32_t so = SWZ(r, q);
            CP_ASYNC16(base + 2 * ATB + so,       gBh + go);
            CP_ASYNC16(base + 2 * ATB + BTB + so, gBl + go);
        }
    };

    float acc[4][8][4];
#pragma unroll
    for (int i = 0; i < 4; i++)
#pragma unroll
        for (int j = 0; j < 8; j++)
#pragma unroll
            for (int k = 0; k < 4; k++) acc[i][j][k] = 0.f;

    // ldmatrix per-lane address components
    int a_row = lane & 15, a_ch = lane >> 4;                     // A x4 mapping
    int b_row = ((lane >> 4) << 3) + (lane & 7), b_ch = (lane >> 3) & 1;  // B x4

    load_chunk(0, 0); CP_COMMIT();
    load_chunk(1, 1); CP_COMMIT();

    for (int c = 0; c < nc; c++) {
        if (c + 1 < nc) CP_WAIT1(); else CP_WAIT0();
        __syncthreads();
        if (c + 2 < nc) { load_chunk(c + 2, (c + 2) % 3); CP_COMMIT(); }

        int s = c % 3;
        uint32_t sAh_ = sb + s * STG;
        uint32_t sAl_ = sAh_ + ATB;
        uint32_t sBh_ = sAh_ + 2 * ATB;
        uint32_t sBl_ = sBh_ + BTB;

#pragma unroll
        for (int kk = 0; kk < 2; kk++) {
            uint32_t ah[4][4], al_[4][4];
#pragma unroll
            for (int mt = 0; mt < 4; mt++) {
                uint32_t off = SWZ(wm * 64 + mt * 16 + a_row, 2 * kk + a_ch);
                ldm_x4(ah[mt],  sAh_ + off);
                ldm_x4(al_[mt], sAl_ + off);
            }
#pragma unroll
            for (int ntp = 0; ntp < 4; ntp++) {
                uint32_t boff = SWZ(wn * 64 + ntp * 16 + b_row, 2 * kk + b_ch);
                uint32_t bh[4], bl[4];
                ldm_x4(bh, sBh_ + boff);
                ldm_x4(bl, sBl_ + boff);
#pragma unroll
                for (int mt = 0; mt < 4; mt++) {
                    mma_bf16(acc[mt][2 * ntp],     ah[mt],  bh + 0);
                    mma_bf16(acc[mt][2 * ntp],     ah[mt],  bl + 0);
                    mma_bf16(acc[mt][2 * ntp],     al_[mt], bh + 0);
                    mma_bf16(acc[mt][2 * ntp + 1], ah[mt],  bh + 2);
                    mma_bf16(acc[mt][2 * ntp + 1], ah[mt],  bl + 2);
                    mma_bf16(acc[mt][2 * ntp + 1], al_[mt], bh + 2);
                }
            }
        }
    }

    // Epilogue
    long zco = zb * sCo + zi * sCi;
    int mrow = lane >> 2, nc2 = (lane & 3) * 2;
#pragma unroll
    for (int mt = 0; mt < 4; mt++) {
#pragma unroll
        for (int nt = 0; nt < 8; nt++) {
#pragma unroll
            for (int e = 0; e < 4; e++) {
                int gr = m0 + wm * 64 + mt * 16 + mrow + ((e >> 1) << 3);
                int gn = n0 + wn * 64 + nt * 8 + nc2 + (e & 1);
                float v = acc[mt][nt][e] * alpha;
                if (bias) v += bias[gn];
                long off = zco + (long)gr * ldc + gn;
                if (res) v += res[off];
                if (act == 1)      v = fmaxf(v, 0.f);
                else if (act == 2) v = 1.f / (1.f + __expf(-v));
                else if (act == 3) { v = 1.f / (1.f + __expf(-v)); v = f1[off] + v * f2[off]; }
                if (C) C[off] = v;
                if (Ch) {
                    bf h = __float2bfloat16(v);
                    Ch[off] = h;
                    Cl[off] = __float2bfloat16(v - __bfloat162float(h));
                }
            }
        }
    }
}

// ===========================================================================
// FlashAttention-2 (unchanged from R9): per (b,h,128-query tile)
// ===========================================================================
#define ADDR8(r, c)  ((uint32_t)((r) * 128 + (((c) ^ ((r) & 7)) << 4)))
#define ADDR16(r, c) ((uint32_t)((r) * 256 + ((((c) & 8) | (((c) & 7) ^ ((r) & 7))) << 4)))

__global__ void __launch_bounds__(256, 1) flash_attn_kernel(
    const bf* __restrict__ qkvh, const bf* __restrict__ qkvl,
    const bf* __restrict__ vth,  const bf* __restrict__ vtl,
    bf* __restrict__ oh, bf* __restrict__ ol)
{
    extern __shared__ char smem[];
    uint32_t sb = smem_to_u32(smem);
    const uint32_t QH = 0, QL = 16384, ST0 = 32768;

    int tid = threadIdx.x, wid = tid >> 5, lane = tid & 31;
    int z = blockIdx.y, b = z >> 3, hh = z & 7;
    int q0 = blockIdx.x * 128;

    const bf* gQh = qkvh + ((long)b * 2048 + q0) * 1536 + hh * 64;
    const bf* gQl = qkvl + ((long)b * 2048 + q0) * 1536 + hh * 64;
    const bf* gKh = qkvh + (long)b * 2048 * 1536 + 512 + hh * 64;
    const bf* gKl = qkvl + (long)b * 2048 * 1536 + 512 + hh * 64;
    const bf* gVh = vth + (long)z * 64 * 2048;
    const bf* gVl = vtl + (long)z * 64 * 2048;

    auto loadKV = [&](int j, int s) {
        uint32_t st = sb + ST0 + s * 65536;
#pragma unroll
        for (int i = tid; i < 1024; i += 256) {
            int r = i >> 3, c = i & 7;
            long go = (long)(j * 128 + r) * 1536 + c * 8;
            uint32_t so = ADDR8(r, c);
            CP_ASYNC16(st + so,         gKh + go);
            CP_ASYNC16(st + 16384 + so, gKl + go);
        }
#pragma unroll
        for (int i = tid; i < 1024; i += 256) {
            int r = i >> 4, c = i & 15;
            long go = (long)r * 2048 + j * 128 + c * 8;
            uint32_t so = ADDR16(r, c);
            CP_ASYNC16(st + 32768 + so, gVh + go);
            CP_ASYNC16(st + 49152 + so, gVl + go);
        }
    };

#pragma unroll
    for (int i = tid; i < 1024; i += 256) {
        int r = i >> 3, c = i & 7;
        long go = (long)r * 1536 + c * 8;
        uint32_t so = ADDR8(r, c);
        CP_ASYNC16(sb + QH + so, gQh + go);
        CP_ASYNC16(sb + QL + so, gQl + go);
    }
    loadKV(0, 0); CP_COMMIT();
    loadKV(1, 1); CP_COMMIT();

    int a_row = lane & 15, a_ch = lane >> 4;
    int b_row = ((lane >> 4) << 3) + (lane & 7), b_ch = (lane >> 3) & 1;

    uint32_t qh[4][4], ql[4][4];
    float accO[8][4];
#pragma unroll
    for (int i = 0; i < 8; i++)
#pragma unroll
        for (int e = 0; e < 4; e++) accO[i][e] = 0.f;
    float mrow[2] = {-1e30f, -1e30f}, lrow[2] = {0.f, 0.f};

    for (int j = 0; j < 16; j++) {
        if (j < 15) CP_WAIT1(); else CP_WAIT0();
        __syncthreads();
        if (j == 0) {
#pragma unroll
            for (int kk = 0; kk < 4; kk++) {
                uint32_t off = ADDR8(wid * 16 + a_row, 2 * kk + a_ch);
                ldm_x4(qh[kk], sb + QH + off);
                ldm_x4(ql[kk], sb + QL + off);
            }
        }
        uint32_t st = sb + ST0 + (j & 1) * 65536;

        float s[16][4];
#pragma unroll
        for (int i = 0; i < 16; i++)
#pragma unroll
            for (int e = 0; e < 4; e++) s[i][e] = 0.f;
#pragma unroll
        for (int kk = 0; kk < 4; kk++) {
#pragma unroll
            for (int ntp = 0; ntp < 8; ntp++) {
                uint32_t off = ADDR8(ntp * 16 + b_row, 2 * kk + b_ch);
                uint32_t bh[4], bl[4];
                ldm_x4(bh, st + off);
                ldm_x4(bl, st + 16384 + off);
                mma_bf16(s[2 * ntp],     qh[kk], bh + 0);
                mma_bf16(s[2 * ntp],     qh[kk], bl + 0);
                mma_bf16(s[2 * ntp],     ql[kk], bh + 0);
                mma_bf16(s[2 * ntp + 1], qh[kk], bh + 2);
                mma_bf16(s[2 * ntp + 1], qh[kk], bl + 2);
                mma_bf16(s[2 * ntp + 1], ql[kk], bh + 2);
            }
        }
#pragma unroll
        for (int i = 0; i < 16; i++)
#pragma unroll
            for (int e = 0; e < 4; e++) s[i][e] *= 0.125f;

#pragma unroll
        for (int h2 = 0; h2 < 2; h2++) {
            float vm = -1e30f;
#pragma unroll
            for (int nt = 0; nt < 16; nt++)
                vm = fmaxf(vm, fmaxf(s[nt][2 * h2], s[nt][2 * h2 + 1]));
            vm = fmaxf(vm, __shfl_xor_sync(0xffffffffu, vm, 1));
            vm = fmaxf(vm, __shfl_xor_sync(0xffffffffu, vm, 2));
            float mn = fmaxf(mrow[h2], vm);
            float scale = __expf(mrow[h2] - mn);
            mrow[h2] = mn;
            float ps = 0.f;
#pragma unroll
            for (int nt = 0; nt < 16; nt++) {
                float e0 = __expf(s[nt][2 * h2] - mn);
                float e1 = __expf(s[nt][2 * h2 + 1] - mn);
                s[nt][2 * h2] = e0; s[nt][2 * h2 + 1] = e1;
                ps += e0 + e1;
            }
            ps += __shfl_xor_sync(0xffffffffu, ps, 1);
            ps += __shfl_xor_sync(0xffffffffu, ps, 2);
            lrow[h2] = lrow[h2] * scale + ps;
#pragma unroll
            for (int nt2 = 0; nt2 < 8; nt2++) {
                accO[nt2][2 * h2]     *= scale;
                accO[nt2][2 * h2 + 1] *= scale;
            }
        }

#pragma unroll
        for (int kt = 0; kt < 8; kt++) {
            uint32_t Ph[4], Pl[4];
#pragma unroll
            for (int jj = 0; jj < 4; jj++) {
                float va = s[2 * kt + (jj >> 1)][(jj & 1) * 2];
                float vb = s[2 * kt + (jj >> 1)][(jj & 1) * 2 + 1];
                bf ha = __float2bfloat16(va), hb = __float2bfloat16(vb);
                float ra = va - __bfloat162float(ha), rb = vb - __bfloat162float(hb);
                Ph[jj] = (uint32_t)__bfloat16_as_ushort(ha) |
                         ((uint32_t)__bfloat16_as_ushort(hb) << 16);
                Pl[jj] = (uint32_t)__bfloat16_as_ushort(__float2bfloat16(ra)) |
                         ((uint32_t)__bfloat16_as_ushort(__float2bfloat16(rb)) << 16);
            }
#pragma unroll
            for (int np = 0; np < 4; np++) {
                uint32_t off = ADDR16(np * 16 + b_row, 2 * kt + b_ch);
                uint32_t vh[4], vl[4];
                ldm_x4(vh, st + 32768 + off);
                ldm_x4(vl, st + 49152 + off);
                mma_bf16(accO[2 * np],     Ph, vh + 0);
                mma_bf16(accO[2 * np],     Ph, vl + 0);
                mma_bf16(accO[2 * np],     Pl, vh + 0);
                mma_bf16(accO[2 * np + 1], Ph, vh + 2);
                mma_bf16(accO[2 * np + 1], Ph, vl + 2);
                mma_bf16(accO[2 * np + 1], Pl, vh + 2);
            }
        }
        __syncthreads();
        if (j + 2 < 16) { loadKV(j + 2, j & 1); CP_COMMIT(); }
    }

    float inv0 = 1.f / lrow[0], inv1 = 1.f / lrow[1];
    long tok0 = (long)b * 2048 + q0 + wid * 16 + (lane >> 2);
    int colb = hh * 64 + (lane & 3) * 2;
#pragma unroll
    for (int nt2 = 0; nt2 < 8; nt2++) {
#pragma unroll
        for (int e = 0; e < 4; e++) {
            long row = tok0 + 8 * (e >> 1);
            int col = colb + nt2 * 8 + (e & 1);
            float v = accO[nt2][e] * ((e >> 1) ? inv1 : inv0);
            bf h = __float2bfloat16(v);
            long off = row * 512 + col;
            oh[off] = h;
            ol[off] = __float2bfloat16(v - __bfloat162float(h));
        }
    }
}

// ===========================================================================
// Aux kernels
// ===========================================================================
__device__ __forceinline__ float blk_reduce_sum(float v) {
    __shared__ float sh[8];
    int t = threadIdx.x;
#pragma unroll
    for (int o = 16; o; o >>= 1) v += __shfl_down_sync(0xffffffffu, v, o);
    if ((t & 31) == 0) sh[t >> 5] = v;
    __syncthreads();
    if (t < 32) {
        float w = (t < 8) ? sh[t] : 0.f;
#pragma unroll
        for (int o = 4; o; o >>= 1) w += __shfl_down_sync(0xffffffffu, w, o);
        if (t == 0) sh[0] = w;
    }
    __syncthreads();
    float r = sh[0];
    __syncthreads();
    return r;
}

// LayerNorm: fp32 out (stride D) and/or split-bf16 out (stride ldy)
__global__ void ln_kernel(const float* __restrict__ x, const float* __restrict__ g,
                          const float* __restrict__ b, float* __restrict__ yf,
                          bf* __restrict__ yh, bf* __restrict__ yl, int D, int ldy)
{
    long row = blockIdx.x;
    const float* xr = x + row * (long)D;
    float s = 0.f;
    for (int i = threadIdx.x; i < D; i += 256) s += xr[i];
    float mean = blk_reduce_sum(s) / (float)D;
    float vs = 0.f;
    for (int i = threadIdx.x; i < D; i += 256) { float d = xr[i] - mean; vs += d * d; }
    float var = blk_reduce_sum(vs) / (float)D;
    float rstd = rsqrtf(var + 1e-5f);
    for (int i = threadIdx.x; i < D; i += 256) {
        float v = (xr[i] - mean) * rstd * g[i] + b[i];
        if (yf) yf[row * (long)D + i] = v;
        if (yh) {
            long o = row * (long)ldy + i;
            bf h = __float2bfloat16(v);
            yh[o] = h;
            yl[o] = __float2bfloat16(v - __bfloat162float(h));
        }
    }
}

// fp32 -> split bf16, with output row stride (rowlen divides 4-aligned work)
__global__ void split_kernel(const float* __restrict__ x, bf* __restrict__ h,
                             bf* __restrict__ l, long n, int rowlen, int ldo)
{
    long i = ((long)blockIdx.x * 256 + threadIdx.x) * 4;
    if (i < n) {
        float4 v = *(const float4*)(x + i);
        float a[4] = {v.x, v.y, v.z, v.w};
        long off = (i / rowlen) * (long)ldo + (i % rowlen);
#pragma unroll
        for (int j = 0; j < 4; j++) {
            bf hh = __float2bfloat16(a[j]);
            h[off + j] = hh;
            l[off + j] = __float2bfloat16(a[j] - __bfloat162float(hh));
        }
    }
}

// All weight transposes + splits in ONE launch. W[K,N] fp32 -> Th/Tl [N,K] bf16.
struct WTDesc { const float* W; bf* Th; bf* Tl; int K; int N; int cum; };
struct WTArgs { WTDesc m[8]; };

__global__ void wtrans_all_kernel(WTArgs args)
{
    __shared__ float t[32][33];
    int bid = blockIdx.x;
    int mi = 0;
#pragma unroll
    for (int i = 0; i < 8; i++)
        if (bid >= args.m[i].cum) mi = i + 1;
    const WTDesc& d = args.m[mi];
    int local = bid - (mi ? args.m[mi - 1].cum : 0);
    int ktiles = d.K >> 5;
    int k0 = (local % ktiles) * 32, n0 = (local / ktiles) * 32;

    int x = threadIdx.x, y = threadIdx.y;   // 32 x 8
#pragma unroll
    for (int i = 0; i < 32; i += 8)
        t[y + i][x] = d.W[(long)(k0 + y + i) * d.N + n0 + x];
    __syncthreads();
#pragma unroll
    for (int i = 0; i < 32; i += 8) {
        float v = t[x][y + i];
        bf h = __float2bfloat16(v);
        long o = (long)(n0 + y + i) * d.K + k0 + x;
        d.Th[o] = h;
        d.Tl[o] = __float2bfloat16(v - __bfloat162float(h));
    }
}

// V transpose (bf16): qkv[:,1024+h*64 : +64] -> vt[z][64][2048]
__global__ void vtrans_kernel(const bf* __restrict__ qh, const bf* __restrict__ ql,
                              bf* __restrict__ vh, bf* __restrict__ vl)
{
    __shared__ bf th[32][33], tl[32][33];
    int z = blockIdx.z; int b = z >> 3, hh = z & 7;
    int k0 = blockIdx.x * 32, n0 = blockIdx.y * 32;
    int x = threadIdx.x, y = threadIdx.y;
    const long ibase = (long)b * 2048 * 1536 + 1024 + hh * 64;
#pragma unroll
    for (int i = 0; i < 32; i += 8) {
        long go = ibase + (long)(k0 + y + i) * 1536 + n0 + x;
        th[y + i][x] = qh[go];
        tl[y + i][x] = ql[go];
    }
    __syncthreads();
    const long obase = (long)z * 64 * 2048;
#pragma unroll
    for (int i = 0; i < 32; i += 8) {
        long o = obase + (long)(n0 + y + i) * 2048 + k0 + x;
        vh[o] = th[x][y + i];
        vl[o] = tl[x][y + i];
    }
}

// Pool: pooled[b][h] = mean_s hidden[b][s][h]
__global__ void pool_mean_kernel(const float* __restrict__ hs, float* __restrict__ pooled)
{
    int b = blockIdx.y;
    int h = blockIdx.x * 256 + threadIdx.x;
    const float* p = hs + (long)b * SS * HH + h;
    float sum = 0.f;
    for (int s = 0; s < SS; s++) sum += p[(long)s * HH];
    pooled[b * HH + h] = sum * (1.f / SS);
}

// Complexity assessor MLP (tiny)
__global__ void ca_kernel(const float* __restrict__ pooled,
                          const float* __restrict__ w1, const float* __restrict__ b1,
                          const float* __restrict__ w2, const float* __restrict__ b2,
                          const float* __restrict__ w3, const float* __restrict__ b3,
                          float* __restrict__ scores_out)
{
    __shared__ float h1[BB][256];
    __shared__ float h2[BB][32];
    int t = threadIdx.x;
    for (int b = 0; b < BB; b++) {
        float acc = b1[t];
        for (int k = 0; k < HH; k++) acc = fmaf(pooled[b * HH + k], w1[k * 256 + t], acc);
        h1[b][t] = fmaxf(acc, 0.f);
    }
    __syncthreads();
    if (t < 32) {
        for (int b = 0; b < BB; b++) {
            float acc = b2[t];
            for (int k = 0; k < 256; k++) acc = fmaf(h1[b][k], w2[k * 32 + t], acc);
            h2[b][t] = fmaxf(acc, 0.f);
        }
    }
    __syncthreads();
    if (t < BB) {
        float acc = b3[0];
        for (int k = 0; k < 32; k++) acc = fmaf(h2[t][k], w3[k], acc);
        scores_out[t] = 1.f / (1.f + expf(-acc));
    }
}

// ===========================================================================
// Host
// ===========================================================================
static void launch_gemm(const bf* Ah, const bf* Al, const bf* Bh, const bf* Bl,
                        const float* bias, const float* res,
                        const float* f1, const float* f2,
                        float* C, bf* Ch, bf* Cl,
                        int M, int N, int K, int lda, int ldb, int ldc,
                        float alpha, int act)
{
    int sm = 3 * (2 * 256 * 64 + 2 * 128 * 64);   // 147456
    cudaFuncSetAttribute(gemm_tc_kernel, cudaFuncAttributeMaxDynamicSharedMemorySize, sm);
    dim3 grid(N / 128, M / 256, 1);
    gemm_tc_kernel<<<grid, 256, sm>>>(Ah, Al, Bh, Bl, bias, res, f1, f2, C, Ch, Cl,
        K, lda, ldb, ldc, 0, 0, 0, 0, 0, 0, 1, alpha, act);
}

#define SYM(p, s) do { void* _t; cudaGetSymbolAddress(&_t, s); p = (decltype(p))_t; } while (0)

extern "C" void kernel_launch(void* const* d_in, const int* in_sizes, int n_in,
                              void* d_out, int out_size)
{
    const float* hs    = (const float*)d_in[0];
    const float* ca_w1 = (const float*)d_in[1];
    const float* ca_b1 = (const float*)d_in[2];
    const float* ca_w2 = (const float*)d_in[3];
    const float* ca_b2 = (const float*)d_in[4];
    const float* ca_w3 = (const float*)d_in[5];
    const float* ca_b3 = (const float*)d_in[6];
    const float* rp_w  = (const float*)d_in[7];
    const float* rp_b  = (const float*)d_in[8];
    const float* rn_g  = (const float*)d_in[9];
    const float* rn_b  = (const float*)d_in[10];
    const float* ln1_g = (const float*)d_in[11];
    const float* ln1_b = (const float*)d_in[12];
    const float* wqkv  = (const float*)d_in[13];
    const float* bqkv  = (const float*)d_in[14];
    const float* wo    = (const float*)d_in[15];
    const float* bo    = (const float*)d_in[16];
    const float* ln2_g = (const float*)d_in[17];
    const float* ln2_b = (const float*)d_in[18];
    const float* ff1_w = (const float*)d_in[19];
    const float* ff1_b = (const float*)d_in[20];
    const float* ff2_w = (const float*)d_in[21];
    const float* ff2_b = (const float*)d_in[22];
    const float* op_w  = (const float*)d_in[23];
    const float* op_b  = (const float*)d_in[24];
    const float* on_g  = (const float*)d_in[25];
    const float* on_b  = (const float*)d_in[26];
    const float* gw1   = (const float*)d_in[27];
    const float* gb1   = (const float*)d_in[28];
    const float* gw2   = (const float*)d_in[29];
    const float* gb2   = (const float*)d_in[30];

    float* out = (float*)d_out;
    float* cs  = out + NTOK * HH;

    float *pooled, *r, *tmpf, *reason;
    SYM(pooled, d_pooled); SYM(r, d_r); SYM(tmpf, d_tmpf); SYM(reason, d_reason);
    bf *cat_h, *cat_l, *y_h, *y_l, *qkv_h, *qkv_l, *vt_h, *vt_l;
    bf *o_h, *o_l, *ff_h, *ff_l, *rs_h, *rs_l, *t2_h, *t2_l;
    SYM(cat_h, d_cat_h); SYM(cat_l, d_cat_l); SYM(y_h, d_y_h); SYM(y_l, d_y_l);
    SYM(qkv_h, d_qkv_h); SYM(qkv_l, d_qkv_l);
    SYM(vt_h, d_vt_h); SYM(vt_l, d_vt_l);
    SYM(o_h, d_o_h); SYM(o_l, d_o_l); SYM(ff_h, d_ff_h); SYM(ff_l, d_ff_l);
    SYM(rs_h, d_rs_h); SYM(rs_l, d_rs_l);
    SYM(t2_h, d_t2_h); SYM(t2_l, d_t2_l);
    bf *rpT_h, *rpT_l, *qkvT_h, *qkvT_l, *woT_h, *woT_l, *ff1T_h, *ff1T_l;
    bf *ff2T_h, *ff2T_l, *opT_h, *opT_l, *g1T_h, *g1T_l, *g2T_h, *g2T_l;
    SYM(rpT_h, d_rpT_h); SYM(rpT_l, d_rpT_l); SYM(qkvT_h, d_qkvT_h); SYM(qkvT_l, d_qkvT_l);
    SYM(woT_h, d_woT_h); SYM(woT_l, d_woT_l); SYM(ff1T_h, d_ff1T_h); SYM(ff1T_l, d_ff1T_l);
    SYM(ff2T_h, d_ff2T_h); SYM(ff2T_l, d_ff2T_l); SYM(opT_h, d_opT_h); SYM(opT_l, d_opT_l);
    SYM(g1T_h, d_g1T_h); SYM(g1T_l, d_g1T_l); SYM(g2T_h, d_g2T_h); SYM(g2T_l, d_g2T_l);

    // -- all weight transposes + splits in one launch --
    {
        WTArgs wa;
        WTDesc ds[8] = {
            {rp_w,  rpT_h,  rpT_l,  1024, 512,  0},
            {wqkv,  qkvT_h, qkvT_l, 512,  1536, 0},
            {wo,    woT_h,  woT_l,  512,  512,  0},
            {ff1_w, ff1T_h, ff1T_l, 512,  2048, 0},
            {ff2_w, ff2T_h, ff2T_l, 2048, 512,  0},
            {op_w,  opT_h,  opT_l,  512,  1024, 0},
            {gw1,   g1T_h,  g1T_l,  2048, 1024, 0},
            {gw2,   g2T_h,  g2T_l,  1024, 1024, 0},
        };
        int cum = 0;
        for (int i = 0; i < 8; i++) {
            cum += (ds[i].K >> 5) * (ds[i].N >> 5);
            ds[i].cum = cum;
            wa.m[i] = ds[i];
        }
        wtrans_all_kernel<<<cum, dim3(32, 8)>>>(wa);
    }

    // -- complexity assessor --
    pool_mean_kernel<<<dim3(HH / 256, BB), 256>>>(hs, pooled);
    ca_kernel<<<1, 256>>>(pooled, ca_w1, ca_b1, ca_w2, ca_b2, ca_w3, ca_b3, cs);

    // -- split hidden states into cat[:, 0:1024] --
    split_kernel<<<(int)(NTOK * HH / 4 / 256), 256>>>(hs, cat_h, cat_l, NTOK * HH, 1024, 2048);

    // -- reasoning proj + pre-norm --
    launch_gemm(cat_h, cat_l, rpT_h, rpT_l, rp_b, nullptr, nullptr, nullptr,
                r, nullptr, nullptr, 8192, 512, 1024, 2048, 1024, 512, 1.f, 0);
    ln_kernel<<<8192, 256>>>(r, rn_g, rn_b, r, nullptr, nullptr, 512, 512);

    // -- attention --
    ln_kernel<<<8192, 256>>>(r, ln1_g, ln1_b, nullptr, y_h, y_l, 512, 512);
    launch_gemm(y_h, y_l, qkvT_h, qkvT_l, bqkv, nullptr, nullptr, nullptr,
                nullptr, qkv_h, qkv_l, 8192, 1536, 512, 512, 512, 1536, 1.f, 0);
    vtrans_kernel<<<dim3(64, 2, 32), dim3(32, 8)>>>(qkv_h, qkv_l, vt_h, vt_l);
    {
        cudaFuncSetAttribute(flash_attn_kernel,
                             cudaFuncAttributeMaxDynamicSharedMemorySize, 163840);
        dim3 grid(16, 32);
        flash_attn_kernel<<<grid, 256, 163840>>>(qkv_h, qkv_l, vt_h, vt_l, o_h, o_l);
    }
    // r = r + o @ wo + bo
    launch_gemm(o_h, o_l, woT_h, woT_l, bo, r, nullptr, nullptr,
                r, nullptr, nullptr, 8192, 512, 512, 512, 512, 512, 1.f, 0);

    // -- FFN --
    ln_kernel<<<8192, 256>>>(r, ln2_g, ln2_b, nullptr, y_h, y_l, 512, 512);
    launch_gemm(y_h, y_l, ff1T_h, ff1T_l, ff1_b, nullptr, nullptr, nullptr,
                nullptr, ff_h, ff_l, 8192, 2048, 512, 512, 512, 2048, 1.f, 1);
    launch_gemm(ff_h, ff_l, ff2T_h, ff2T_l, ff2_b, r, nullptr, nullptr,
                r, nullptr, nullptr, 8192, 512, 2048, 2048, 2048, 512, 1.f, 0);

    // -- output projection + norm (reasoned also written into cat[:, 1024:2048]) --
    split_kernel<<<(int)(NTOK * RR / 4 / 256), 256>>>(r, rs_h, rs_l, NTOK * RR, 512, 512);
    launch_gemm(rs_h, rs_l, opT_h, opT_l, op_b, nullptr, nullptr, nullptr,
                tmpf, nullptr, nullptr, 8192, 1024, 512, 512, 512, 1024, 1.f, 0);
    ln_kernel<<<8192, 256>>>(tmpf, on_g, on_b, reason, cat_h + 1024, cat_l + 1024, 1024, 2048);

    // -- integration gate: single K=2048 GEMM over [hs | reasoned], relu fused --
    launch_gemm(cat_h, cat_l, g1T_h, g1T_l, gb1, nullptr, nullptr, nullptr,
                nullptr, t2_h, t2_l, 8192, 1024, 2048, 2048, 2048, 1024, 1.f, 1);
    // g2 + sigmoid + final blend fused: out = hs + sigmoid(.)*reason
    launch_gemm(t2_h, t2_l, g2T_h, g2T_l, gb2, nullptr, hs, reason,
                out, nullptr, nullptr, 8192, 1024, 1024, 1024, 1024, 1024, 1.f, 3);
}

// round 14
// speedup vs baseline: 1.2810x; 1.2810x over previous
#include <cuda_runtime.h>
#include <cuda_bf16.h>
#include <cstdint>
#include <math.h>

typedef __nv_bfloat16 bf;

// Problem constants
#define BB 4
#define SS 2048
#define HH 1024
#define RR 512
#define NHEAD 8
#define HDIM 64
#define NTOK 8192L   // B*S

// ===========================================================================
// Baseline-PTX helpers (sm_80-era: ldmatrix / mma.sync / cp.async)
// ===========================================================================
__device__ __forceinline__ uint32_t smem_to_u32(const void* p) {
    uint32_t a;
    asm("{ .reg .u64 t; cvta.to.shared.u64 t, %1; cvt.u32.u64 %0, t; }" : "=r"(a) : "l"(p));
    return a;
}
__device__ __forceinline__ void ldm_x4(uint32_t* r, uint32_t addr) {
    asm volatile("ldmatrix.sync.aligned.m8n8.x4.shared.b16 {%0,%1,%2,%3}, [%4];"
                 : "=r"(r[0]), "=r"(r[1]), "=r"(r[2]), "=r"(r[3]) : "r"(addr));
}
__device__ __forceinline__ void mma_bf16(float* d, const uint32_t* a, const uint32_t* b) {
    asm volatile("mma.sync.aligned.m16n8k16.row.col.f32.bf16.bf16.f32 "
                 "{%0,%1,%2,%3}, {%4,%5,%6,%7}, {%8,%9}, {%0,%1,%2,%3};"
                 : "+f"(d[0]), "+f"(d[1]), "+f"(d[2]), "+f"(d[3])
                 : "r"(a[0]), "r"(a[1]), "r"(a[2]), "r"(a[3]), "r"(b[0]), "r"(b[1]));
}
#define CP_ASYNC16(dst, src) \
    asm volatile("cp.async.cg.shared.global [%0], [%1], 16;" :: "r"(dst), "l"(src))
#define CP_COMMIT() asm volatile("cp.async.commit_group;" ::: "memory")
#define CP_WAIT1()  asm volatile("cp.async.wait_group 1;" ::: "memory")
#define CP_WAIT0()  asm volatile("cp.async.wait_group 0;" ::: "memory")

// Swizzled smem offset: rows of 64B (32 bf16), 4x 16B chunks, XOR by (row>>1)&3
#define SWZ(row, c) ((uint32_t)((row) * 64 + (((c) ^ (((row) >> 1) & 3)) << 4)))

// ===========================================================================
// Scratch (static device globals; no allocation allowed)
// ===========================================================================
__device__ float d_pooled[BB * HH];
__device__ float d_r[NTOK * RR];
__device__ float d_tmpf[NTOK * HH];
__device__ float d_reason[NTOK * HH];

__device__ bf d_cat_h[NTOK * 2 * HH], d_cat_l[NTOK * 2 * HH];   // [hs | reasoned]
__device__ bf d_y_h[NTOK * RR],   d_y_l[NTOK * RR];
__device__ bf d_qkv_h[NTOK * 3 * RR], d_qkv_l[NTOK * 3 * RR];
__device__ bf d_vt_h[(long)BB * NHEAD * HDIM * SS], d_vt_l[(long)BB * NHEAD * HDIM * SS];
__device__ bf d_o_h[NTOK * RR],   d_o_l[NTOK * RR];
__device__ bf d_ff_h[NTOK * 4 * RR], d_ff_l[NTOK * 4 * RR];
__device__ bf d_rs_h[NTOK * RR],  d_rs_l[NTOK * RR];
__device__ bf d_t2_h[NTOK * HH],  d_t2_l[NTOK * HH];
// transposed + split weights ([N,K] bf16)
__device__ bf d_rpT_h[RR * HH],       d_rpT_l[RR * HH];
__device__ bf d_qkvT_h[3 * RR * RR],  d_qkvT_l[3 * RR * RR];
__device__ bf d_woT_h[RR * RR],       d_woT_l[RR * RR];
__device__ bf d_ff1T_h[4 * RR * RR],  d_ff1T_l[4 * RR * RR];
__device__ bf d_ff2T_h[RR * 4 * RR],  d_ff2T_l[RR * 4 * RR];
__device__ bf d_opT_h[HH * RR],       d_opT_l[HH * RR];
__device__ bf d_g1T_h[HH * 2 * HH],   d_g1T_l[HH * 2 * HH];
__device__ bf d_g2T_h[HH * HH],       d_g2T_l[HH * HH];

// ===========================================================================
// Warp-MMA split-bf16 GEMM (R9-proven core): D = Ah*Bh + Ah*Bl + Al*Bh
//   A: [M,K] bf16 (K-major), B: [N,K] bf16 (K-major)
//   CTA tile 128 x 128, BK=32, 8 warps (2m x 4n), warp tile 64 x 32.
//   2-stage cp.async pipeline, 2 CTAs/SM.
//   act: 0 none, 1 relu, 2 sigmoid, 3 fused gate: C = f1 + sigmoid(v)*f2
// ===========================================================================
__global__ void __launch_bounds__(256, 2) gemm_tc_kernel(
    const bf* __restrict__ Ah, const bf* __restrict__ Al,
    const bf* __restrict__ Bh, const bf* __restrict__ Bl,
    const float* __restrict__ bias, const float* __restrict__ res,
    const float* __restrict__ f1, const float* __restrict__ f2,
    float* __restrict__ C, bf* __restrict__ Ch, bf* __restrict__ Cl,
    int K, int lda, int ldb, int ldc,
    float alpha, int act)
{
    constexpr int BN  = 128;
    constexpr int ATB = 128 * 64;     // 8192 B per A matrix per stage
    constexpr int BTB = BN * 64;      // 8192 B per B matrix per stage
    constexpr int STG = 2 * ATB + 2 * BTB;

    extern __shared__ char smem[];
    uint32_t sb = smem_to_u32(smem);

    int tid = threadIdx.x, wid = tid >> 5, lane = tid & 31;
    int wm = wid & 1, wn = wid >> 1;

    int m0 = blockIdx.y * 128, n0 = blockIdx.x * BN;
    const bf* gAh = Ah + (long)m0 * lda;
    const bf* gAl = Al + (long)m0 * lda;
    const bf* gBh = Bh + (long)n0 * ldb;
    const bf* gBl = Bl + (long)n0 * ldb;

    const int nc = K >> 5;   // 32-wide K chunks

    auto load_chunk = [&](int c, int s) {
        uint32_t base = sb + s * STG;
        long ko = (long)c << 5;
#pragma unroll
        for (int i = tid; i < 512; i += 256) {          // A: 128 rows x 4 chunks
            int r = i >> 2, q = i & 3;
            long go = (long)r * lda + ko + q * 8;
            uint32_t so = SWZ(r, q);
            CP_ASYNC16(base + so,       gAh + go);
            CP_ASYNC16(base + ATB + so, gAl + go);
        }
#pragma unroll
        for (int i = tid; i < 512; i += 256) {          // B: 128 rows x 4 chunks
            int r = i >> 2, q = i & 3;
            long go = (long)r * ldb + ko + q * 8;
            uint32_t so = SWZ(r, q);
            CP_ASYNC16(base + 2 * ATB + so,       gBh + go);
            CP_ASYNC16(base + 2 * ATB + BTB + so, gBl + go);
        }
    };

    float acc[4][4][4];
#pragma unroll
    for (int i = 0; i < 4; i++)
#pragma unroll
        for (int j = 0; j < 4; j++)
#pragma unroll
            for (int k = 0; k < 4; k++) acc[i][j][k] = 0.f;

    // ldmatrix per-lane address components
    int a_row = lane & 15, a_ch = lane >> 4;                     // A x4 mapping
    int b_row = ((lane >> 4) << 3) + (lane & 7), b_ch = (lane >> 3) & 1;  // B x4

    load_chunk(0, 0); CP_COMMIT();
    if (nc > 1) { load_chunk(1, 1); CP_COMMIT(); }

    for (int c = 0; c < nc; c++) {
        int s = c & 1;
        if (c + 1 < nc) CP_WAIT1(); else CP_WAIT0();
        __syncthreads();

        uint32_t sAh_ = sb + s * STG;
        uint32_t sAl_ = sAh_ + ATB;
        uint32_t sBh_ = sAh_ + 2 * ATB;
        uint32_t sBl_ = sBh_ + BTB;

#pragma unroll
        for (int kk = 0; kk < 2; kk++) {
            uint32_t ah[4][4], al_[4][4];
#pragma unroll
            for (int mt = 0; mt < 4; mt++) {
                uint32_t off = SWZ(wm * 64 + mt * 16 + a_row, 2 * kk + a_ch);
                ldm_x4(ah[mt],  sAh_ + off);
                ldm_x4(al_[mt], sAl_ + off);
            }
#pragma unroll
            for (int ntp = 0; ntp < 2; ntp++) {
                uint32_t boff = SWZ(wn * 32 + ntp * 16 + b_row, 2 * kk + b_ch);
                uint32_t bh[4], bl[4];
                ldm_x4(bh, sBh_ + boff);
                ldm_x4(bl, sBl_ + boff);
#pragma unroll
                for (int mt = 0; mt < 4; mt++) {
                    mma_bf16(acc[mt][2 * ntp],     ah[mt],  bh + 0);
                    mma_bf16(acc[mt][2 * ntp],     ah[mt],  bl + 0);
                    mma_bf16(acc[mt][2 * ntp],     al_[mt], bh + 0);
                    mma_bf16(acc[mt][2 * ntp + 1], ah[mt],  bh + 2);
                    mma_bf16(acc[mt][2 * ntp + 1], ah[mt],  bl + 2);
                    mma_bf16(acc[mt][2 * ntp + 1], al_[mt], bh + 2);
                }
            }
        }
        __syncthreads();
        if (c + 2 < nc) { load_chunk(c + 2, s); CP_COMMIT(); }
    }

    // Epilogue
    int mrow = lane >> 2, nc2 = (lane & 3) * 2;
#pragma unroll
    for (int mt = 0; mt < 4; mt++) {
#pragma unroll
        for (int nt = 0; nt < 4; nt++) {
#pragma unroll
            for (int e = 0; e < 4; e++) {
                int gr = m0 + wm * 64 + mt * 16 + mrow + ((e >> 1) << 3);
                int gn = n0 + wn * 32 + nt * 8 + nc2 + (e & 1);
                float v = acc[mt][nt][e] * alpha;
                if (bias) v += bias[gn];
                long off = (long)gr * ldc + gn;
                if (res) v += res[off];
                if (act == 1)      v = fmaxf(v, 0.f);
                else if (act == 2) v = 1.f / (1.f + __expf(-v));
                else if (act == 3) { v = 1.f / (1.f + __expf(-v)); v = f1[off] + v * f2[off]; }
                if (C) C[off] = v;
                if (Ch) {
                    bf h = __float2bfloat16(v);
                    Ch[off] = h;
                    Cl[off] = __float2bfloat16(v - __bfloat162float(h));
                }
            }
        }
    }
}

// ===========================================================================
// FlashAttention-2 (unchanged, proven): per (b,h,128-query tile)
// ===========================================================================
#define ADDR8(r, c)  ((uint32_t)((r) * 128 + (((c) ^ ((r) & 7)) << 4)))
#define ADDR16(r, c) ((uint32_t)((r) * 256 + ((((c) & 8) | (((c) & 7) ^ ((r) & 7))) << 4)))

__global__ void __launch_bounds__(256, 1) flash_attn_kernel(
    const bf* __restrict__ qkvh, const bf* __restrict__ qkvl,
    const bf* __restrict__ vth,  const bf* __restrict__ vtl,
    bf* __restrict__ oh, bf* __restrict__ ol)
{
    extern __shared__ char smem[];
    uint32_t sb = smem_to_u32(smem);
    const uint32_t QH = 0, QL = 16384, ST0 = 32768;

    int tid = threadIdx.x, wid = tid >> 5, lane = tid & 31;
    int z = blockIdx.y, b = z >> 3, hh = z & 7;
    int q0 = blockIdx.x * 128;

    const bf* gQh = qkvh + ((long)b * 2048 + q0) * 1536 + hh * 64;
    const bf* gQl = qkvl + ((long)b * 2048 + q0) * 1536 + hh * 64;
    const bf* gKh = qkvh + (long)b * 2048 * 1536 + 512 + hh * 64;
    const bf* gKl = qkvl + (long)b * 2048 * 1536 + 512 + hh * 64;
    const bf* gVh = vth + (long)z * 64 * 2048;
    const bf* gVl = vtl + (long)z * 64 * 2048;

    auto loadKV = [&](int j, int s) {
        uint32_t st = sb + ST0 + s * 65536;
#pragma unroll
        for (int i = tid; i < 1024; i += 256) {
            int r = i >> 3, c = i & 7;
            long go = (long)(j * 128 + r) * 1536 + c * 8;
            uint32_t so = ADDR8(r, c);
            CP_ASYNC16(st + so,         gKh + go);
            CP_ASYNC16(st + 16384 + so, gKl + go);
        }
#pragma unroll
        for (int i = tid; i < 1024; i += 256) {
            int r = i >> 4, c = i & 15;
            long go = (long)r * 2048 + j * 128 + c * 8;
            uint32_t so = ADDR16(r, c);
            CP_ASYNC16(st + 32768 + so, gVh + go);
            CP_ASYNC16(st + 49152 + so, gVl + go);
        }
    };

#pragma unroll
    for (int i = tid; i < 1024; i += 256) {
        int r = i >> 3, c = i & 7;
        long go = (long)r * 1536 + c * 8;
        uint32_t so = ADDR8(r, c);
        CP_ASYNC16(sb + QH + so, gQh + go);
        CP_ASYNC16(sb + QL + so, gQl + go);
    }
    loadKV(0, 0); CP_COMMIT();
    loadKV(1, 1); CP_COMMIT();

    int a_row = lane & 15, a_ch = lane >> 4;
    int b_row = ((lane >> 4) << 3) + (lane & 7), b_ch = (lane >> 3) & 1;

    uint32_t qh[4][4], ql[4][4];
    float accO[8][4];
#pragma unroll
    for (int i = 0; i < 8; i++)
#pragma unroll
        for (int e = 0; e < 4; e++) accO[i][e] = 0.f;
    float mrow[2] = {-1e30f, -1e30f}, lrow[2] = {0.f, 0.f};

    for (int j = 0; j < 16; j++) {
        if (j < 15) CP_WAIT1(); else CP_WAIT0();
        __syncthreads();
        if (j == 0) {
#pragma unroll
            for (int kk = 0; kk < 4; kk++) {
                uint32_t off = ADDR8(wid * 16 + a_row, 2 * kk + a_ch);
                ldm_x4(qh[kk], sb + QH + off);
                ldm_x4(ql[kk], sb + QL + off);
            }
        }
        uint32_t st = sb + ST0 + (j & 1) * 65536;

        float s[16][4];
#pragma unroll
        for (int i = 0; i < 16; i++)
#pragma unroll
            for (int e = 0; e < 4; e++) s[i][e] = 0.f;
#pragma unroll
        for (int kk = 0; kk < 4; kk++) {
#pragma unroll
            for (int ntp = 0; ntp < 8; ntp++) {
                uint32_t off = ADDR8(ntp * 16 + b_row, 2 * kk + b_ch);
                uint32_t bh[4], bl[4];
                ldm_x4(bh, st + off);
                ldm_x4(bl, st + 16384 + off);
                mma_bf16(s[2 * ntp],     qh[kk], bh + 0);
                mma_bf16(s[2 * ntp],     qh[kk], bl + 0);
                mma_bf16(s[2 * ntp],     ql[kk], bh + 0);
                mma_bf16(s[2 * ntp + 1], qh[kk], bh + 2);
                mma_bf16(s[2 * ntp + 1], qh[kk], bl + 2);
                mma_bf16(s[2 * ntp + 1], ql[kk], bh + 2);
            }
        }
#pragma unroll
        for (int i = 0; i < 16; i++)
#pragma unroll
            for (int e = 0; e < 4; e++) s[i][e] *= 0.125f;

#pragma unroll
        for (int h2 = 0; h2 < 2; h2++) {
            float vm = -1e30f;
#pragma unroll
            for (int nt = 0; nt < 16; nt++)
                vm = fmaxf(vm, fmaxf(s[nt][2 * h2], s[nt][2 * h2 + 1]));
            vm = fmaxf(vm, __shfl_xor_sync(0xffffffffu, vm, 1));
            vm = fmaxf(vm, __shfl_xor_sync(0xffffffffu, vm, 2));
            float mn = fmaxf(mrow[h2], vm);
            float scale = __expf(mrow[h2] - mn);
            mrow[h2] = mn;
            float ps = 0.f;
#pragma unroll
            for (int nt = 0; nt < 16; nt++) {
                float e0 = __expf(s[nt][2 * h2] - mn);
                float e1 = __expf(s[nt][2 * h2 + 1] - mn);
                s[nt][2 * h2] = e0; s[nt][2 * h2 + 1] = e1;
                ps += e0 + e1;
            }
            ps += __shfl_xor_sync(0xffffffffu, ps, 1);
            ps += __shfl_xor_sync(0xffffffffu, ps, 2);
            lrow[h2] = lrow[h2] * scale + ps;
#pragma unroll
            for (int nt2 = 0; nt2 < 8; nt2++) {
                accO[nt2][2 * h2]     *= scale;
                accO[nt2][2 * h2 + 1] *= scale;
            }
        }

#pragma unroll
        for (int kt = 0; kt < 8; kt++) {
            uint32_t Ph[4], Pl[4];
#pragma unroll
            for (int jj = 0; jj < 4; jj++) {
                float va = s[2 * kt + (jj >> 1)][(jj & 1) * 2];
                float vb = s[2 * kt + (jj >> 1)][(jj & 1) * 2 + 1];
                bf ha = __float2bfloat16(va), hb = __float2bfloat16(vb);
                float ra = va - __bfloat162float(ha), rb = vb - __bfloat162float(hb);
                Ph[jj] = (uint32_t)__bfloat16_as_ushort(ha) |
                         ((uint32_t)__bfloat16_as_ushort(hb) << 16);
                Pl[jj] = (uint32_t)__bfloat16_as_ushort(__float2bfloat16(ra)) |
                         ((uint32_t)__bfloat16_as_ushort(__float2bfloat16(rb)) << 16);
            }
#pragma unroll
            for (int np = 0; np < 4; np++) {
                uint32_t off = ADDR16(np * 16 + b_row, 2 * kt + b_ch);
                uint32_t vh[4], vl[4];
                ldm_x4(vh, st + 32768 + off);
                ldm_x4(vl, st + 49152 + off);
                mma_bf16(accO[2 * np],     Ph, vh + 0);
                mma_bf16(accO[2 * np],     Ph, vl + 0);
                mma_bf16(accO[2 * np],     Pl, vh + 0);
                mma_bf16(accO[2 * np + 1], Ph, vh + 2);
                mma_bf16(accO[2 * np + 1], Ph, vl + 2);
                mma_bf16(accO[2 * np + 1], Pl, vh + 2);
            }
        }
        __syncthreads();
        if (j + 2 < 16) { loadKV(j + 2, j & 1); CP_COMMIT(); }
    }

    float inv0 = 1.f / lrow[0], inv1 = 1.f / lrow[1];
    long tok0 = (long)b * 2048 + q0 + wid * 16 + (lane >> 2);
    int colb = hh * 64 + (lane & 3) * 2;
#pragma unroll
    for (int nt2 = 0; nt2 < 8; nt2++) {
#pragma unroll
        for (int e = 0; e < 4; e++) {
            long row = tok0 + 8 * (e >> 1);
            int col = colb + nt2 * 8 + (e & 1);
            float v = accO[nt2][e] * ((e >> 1) ? inv1 : inv0);
            bf h = __float2bfloat16(v);
            long off = row * 512 + col;
            oh[off] = h;
            ol[off] = __float2bfloat16(v - __bfloat162float(h));
        }
    }
}

// ===========================================================================
// Aux kernels
// ===========================================================================
__device__ __forceinline__ float blk_reduce_sum(float v) {
    __shared__ float sh[8];
    int t = threadIdx.x;
#pragma unroll
    for (int o = 16; o; o >>= 1) v += __shfl_down_sync(0xffffffffu, v, o);
    if ((t & 31) == 0) sh[t >> 5] = v;
    __syncthreads();
    if (t < 32) {
        float w = (t < 8) ? sh[t] : 0.f;
#pragma unroll
        for (int o = 4; o; o >>= 1) w += __shfl_down_sync(0xffffffffu, w, o);
        if (t == 0) sh[0] = w;
    }
    __syncthreads();
    float r = sh[0];
    __syncthreads();
    return r;
}

// LayerNorm: fp32 out (stride D) and/or split-bf16 out (stride ldy)
__global__ void ln_kernel(const float* __restrict__ x, const float* __restrict__ g,
                          const float* __restrict__ b, float* __restrict__ yf,
                          bf* __restrict__ yh, bf* __restrict__ yl, int D, int ldy)
{
    long row = blockIdx.x;
    const float* xr = x + row * (long)D;
    float s = 0.f;
    for (int i = threadIdx.x; i < D; i += 256) s += xr[i];
    float mean = blk_reduce_sum(s) / (float)D;
    float vs = 0.f;
    for (int i = threadIdx.x; i < D; i += 256) { float d = xr[i] - mean; vs += d * d; }
    float var = blk_reduce_sum(vs) / (float)D;
    float rstd = rsqrtf(var + 1e-5f);
    for (int i = threadIdx.x; i < D; i += 256) {
        float v = (xr[i] - mean) * rstd * g[i] + b[i];
        if (yf) yf[row * (long)D + i] = v;
        if (yh) {
            long o = row * (long)ldy + i;
            bf h = __float2bfloat16(v);
            yh[o] = h;
            yl[o] = __float2bfloat16(v - __bfloat162float(h));
        }
    }
}

// fp32 -> split bf16, with output row stride
__global__ void split_kernel(const float* __restrict__ x, bf* __restrict__ h,
                             bf* __restrict__ l, long n, int rowlen, int ldo)
{
    long i = ((long)blockIdx.x * 256 + threadIdx.x) * 4;
    if (i < n) {
        float4 v = *(const float4*)(x + i);
        float a[4] = {v.x, v.y, v.z, v.w};
        long off = (i / rowlen) * (long)ldo + (i % rowlen);
#pragma unroll
        for (int j = 0; j < 4; j++) {
            bf hh = __float2bfloat16(a[j]);
            h[off + j] = hh;
            l[off + j] = __float2bfloat16(a[j] - __bfloat162float(hh));
        }
    }
}

// All weight transposes + splits in ONE launch. W[K,N] fp32 -> Th/Tl [N,K] bf16.
struct WTDesc { const float* W; bf* Th; bf* Tl; int K; int N; int cum; };
struct WTArgs { WTDesc m[8]; };

__global__ void wtrans_all_kernel(WTArgs args)
{
    __shared__ float t[32][33];
    int bid = blockIdx.x;
    int mi = 0;
#pragma unroll
    for (int i = 0; i < 8; i++)
        if (bid >= args.m[i].cum) mi = i + 1;
    const WTDesc& d = args.m[mi];
    int local = bid - (mi ? args.m[mi - 1].cum : 0);
    int ktiles = d.K >> 5;
    int k0 = (local % ktiles) * 32, n0 = (local / ktiles) * 32;

    int x = threadIdx.x, y = threadIdx.y;   // 32 x 8
#pragma unroll
    for (int i = 0; i < 32; i += 8)
        t[y + i][x] = d.W[(long)(k0 + y + i) * d.N + n0 + x];
    __syncthreads();
#pragma unroll
    for (int i = 0; i < 32; i += 8) {
        float v = t[x][y + i];
        bf h = __float2bfloat16(v);
        long o = (long)(n0 + y + i) * d.K + k0 + x;
        d.Th[o] = h;
        d.Tl[o] = __float2bfloat16(v - __bfloat162float(h));
    }
}

// V transpose (bf16): qkv[:,1024+h*64 : +64] -> vt[z][64][2048]
__global__ void vtrans_kernel(const bf* __restrict__ qh, const bf* __restrict__ ql,
                              bf* __restrict__ vh, bf* __restrict__ vl)
{
    __shared__ bf th[32][33], tl[32][33];
    int z = blockIdx.z; int b = z >> 3, hh = z & 7;
    int k0 = blockIdx.x * 32, n0 = blockIdx.y * 32;
    int x = threadIdx.x, y = threadIdx.y;
    const long ibase = (long)b * 2048 * 1536 + 1024 + hh * 64;
#pragma unroll
    for (int i = 0; i < 32; i += 8) {
        long go = ibase + (long)(k0 + y + i) * 1536 + n0 + x;
        th[y + i][x] = qh[go];
        tl[y + i][x] = ql[go];
    }
    __syncthreads();
    const long obase = (long)z * 64 * 2048;
#pragma unroll
    for (int i = 0; i < 32; i += 8) {
        long o = obase + (long)(n0 + y + i) * 2048 + k0 + x;
        vh[o] = th[x][y + i];
        vl[o] = tl[x][y + i];
    }
}

// Pool: pooled[b][h] = mean_s hidden[b][s][h]
__global__ void pool_mean_kernel(const float* __restrict__ hs, float* __restrict__ pooled)
{
    int b = blockIdx.y;
    int h = blockIdx.x * 256 + threadIdx.x;
    const float* p = hs + (long)b * SS * HH + h;
    float sum = 0.f;
    for (int s = 0; s < SS; s++) sum += p[(long)s * HH];
    pooled[b * HH + h] = sum * (1.f / SS);
}

// Complexity assessor MLP (tiny)
__global__ void ca_kernel(const float* __restrict__ pooled,
                          const float* __restrict__ w1, const float* __restrict__ b1,
                          const float* __restrict__ w2, const float* __restrict__ b2,
                          const float* __restrict__ w3, const float* __restrict__ b3,
                          float* __restrict__ scores_out)
{
    __shared__ float h1[BB][256];
    __shared__ float h2[BB][32];
    int t = threadIdx.x;
    for (int b = 0; b < BB; b++) {
        float acc = b1[t];
        for (int k = 0; k < HH; k++) acc = fmaf(pooled[b * HH + k], w1[k * 256 + t], acc);
        h1[b][t] = fmaxf(acc, 0.f);
    }
    __syncthreads();
    if (t < 32) {
        for (int b = 0; b < BB; b++) {
            float acc = b2[t];
            for (int k = 0; k < 256; k++) acc = fmaf(h1[b][k], w2[k * 32 + t], acc);
            h2[b][t] = fmaxf(acc, 0.f);
        }
    }
    __syncthreads();
    if (t < BB) {
        float acc = b3[0];
        for (int k = 0; k < 32; k++) acc = fmaf(h2[t][k], w3[k], acc);
        scores_out[t] = 1.f / (1.f + expf(-acc));
    }
}

// ===========================================================================
// Host
// ===========================================================================
static void launch_gemm(const bf* Ah, const bf* Al, const bf* Bh, const bf* Bl,
                        const float* bias, const float* res,
                        const float* f1, const float* f2,
                        float* C, bf* Ch, bf* Cl,
                        int M, int N, int K, int lda, int ldb, int ldc,
                        float alpha, int act)
{
    int sm = 2 * (2 * 128 * 64 + 2 * 128 * 64);   // 65536
    cudaFuncSetAttribute(gemm_tc_kernel, cudaFuncAttributeMaxDynamicSharedMemorySize, sm);
    dim3 grid(N / 128, M / 128, 1);
    gemm_tc_kernel<<<grid, 256, sm>>>(Ah, Al, Bh, Bl, bias, res, f1, f2, C, Ch, Cl,
        K, lda, ldb, ldc, alpha, act);
}

#define SYM(p, s) do { void* _t; cudaGetSymbolAddress(&_t, s); p = (decltype(p))_t; } while (0)

extern "C" void kernel_launch(void* const* d_in, const int* in_sizes, int n_in,
                              void* d_out, int out_size)
{
    const float* hs    = (const float*)d_in[0];
    const float* ca_w1 = (const float*)d_in[1];
    const float* ca_b1 = (const float*)d_in[2];
    const float* ca_w2 = (const float*)d_in[3];
    const float* ca_b2 = (const float*)d_in[4];
    const float* ca_w3 = (const float*)d_in[5];
    const float* ca_b3 = (const float*)d_in[6];
    const float* rp_w  = (const float*)d_in[7];
    const float* rp_b  = (const float*)d_in[8];
    const float* rn_g  = (const float*)d_in[9];
    const float* rn_b  = (const float*)d_in[10];
    const float* ln1_g = (const float*)d_in[11];
    const float* ln1_b = (const float*)d_in[12];
    const float* wqkv  = (const float*)d_in[13];
    const float* bqkv  = (const float*)d_in[14];
    const float* wo    = (const float*)d_in[15];
    const float* bo    = (const float*)d_in[16];
    const float* ln2_g = (const float*)d_in[17];
    const float* ln2_b = (const float*)d_in[18];
    const float* ff1_w = (const float*)d_in[19];
    const float* ff1_b = (const float*)d_in[20];
    const float* ff2_w = (const float*)d_in[21];
    const float* ff2_b = (const float*)d_in[22];
    const float* op_w  = (const float*)d_in[23];
    const float* op_b  = (const float*)d_in[24];
    const float* on_g  = (const float*)d_in[25];
    const float* on_b  = (const float*)d_in[26];
    const float* gw1   = (const float*)d_in[27];
    const float* gb1   = (const float*)d_in[28];
    const float* gw2   = (const float*)d_in[29];
    const float* gb2   = (const float*)d_in[30];

    float* out = (float*)d_out;
    float* cs  = out + NTOK * HH;

    float *pooled, *r, *tmpf, *reason;
    SYM(pooled, d_pooled); SYM(r, d_r); SYM(tmpf, d_tmpf); SYM(reason, d_reason);
    bf *cat_h, *cat_l, *y_h, *y_l, *qkv_h, *qkv_l, *vt_h, *vt_l;
    bf *o_h, *o_l, *ff_h, *ff_l, *rs_h, *rs_l, *t2_h, *t2_l;
    SYM(cat_h, d_cat_h); SYM(cat_l, d_cat_l); SYM(y_h, d_y_h); SYM(y_l, d_y_l);
    SYM(qkv_h, d_qkv_h); SYM(qkv_l, d_qkv_l);
    SYM(vt_h, d_vt_h); SYM(vt_l, d_vt_l);
    SYM(o_h, d_o_h); SYM(o_l, d_o_l); SYM(ff_h, d_ff_h); SYM(ff_l, d_ff_l);
    SYM(rs_h, d_rs_h); SYM(rs_l, d_rs_l);
    SYM(t2_h, d_t2_h); SYM(t2_l, d_t2_l);
    bf *rpT_h, *rpT_l, *qkvT_h, *qkvT_l, *woT_h, *woT_l, *ff1T_h, *ff1T_l;
    bf *ff2T_h, *ff2T_l, *opT_h, *opT_l, *g1T_h, *g1T_l, *g2T_h, *g2T_l;
    SYM(rpT_h, d_rpT_h); SYM(rpT_l, d_rpT_l); SYM(qkvT_h, d_qkvT_h); SYM(qkvT_l, d_qkvT_l);
    SYM(woT_h, d_woT_h); SYM(woT_l, d_woT_l); SYM(ff1T_h, d_ff1T_h); SYM(ff1T_l, d_ff1T_l);
    SYM(ff2T_h, d_ff2T_h); SYM(ff2T_l, d_ff2T_l); SYM(opT_h, d_opT_h); SYM(opT_l, d_opT_l);
    SYM(g1T_h, d_g1T_h); SYM(g1T_l, d_g1T_l); SYM(g2T_h, d_g2T_h); SYM(g2T_l, d_g2T_l);

    // -- all weight transposes + splits in one launch --
    {
        WTArgs wa;
        WTDesc ds[8] = {
            {rp_w,  rpT_h,  rpT_l,  1024, 512,  0},
            {wqkv,  qkvT_h, qkvT_l, 512,  1536, 0},
            {wo,    woT_h,  woT_l,  512,  512,  0},
            {ff1_w, ff1T_h, ff1T_l, 512,  2048, 0},
            {ff2_w, ff2T_h, ff2T_l, 2048, 512,  0},
            {op_w,  opT_h,  opT_l,  512,  1024, 0},
            {gw1,   g1T_h,  g1T_l,  2048, 1024, 0},
            {gw2,   g2T_h,  g2T_l,  1024, 1024, 0},
        };
        int cum = 0;
        for (int i = 0; i < 8; i++) {
            cum += (ds[i].K >> 5) * (ds[i].N >> 5);
            ds[i].cum = cum;
            wa.m[i] = ds[i];
        }
        wtrans_all_kernel<<<cum, dim3(32, 8)>>>(wa);
    }

    // -- complexity assessor --
    pool_mean_kernel<<<dim3(HH / 256, BB), 256>>>(hs, pooled);
    ca_kernel<<<1, 256>>>(pooled, ca_w1, ca_b1, ca_w2, ca_b2, ca_w3, ca_b3, cs);

    // -- split hidden states into cat[:, 0:1024] --
    split_kernel<<<(int)(NTOK * HH / 4 / 256), 256>>>(hs, cat_h, cat_l, NTOK * HH, 1024, 2048);

    // -- reasoning proj + pre-norm --
    launch_gemm(cat_h, cat_l, rpT_h, rpT_l, rp_b, nullptr, nullptr, nullptr,
                r, nullptr, nullptr, 8192, 512, 1024, 2048, 1024, 512, 1.f, 0);
    ln_kernel<<<8192, 256>>>(r, rn_g, rn_b, r, nullptr, nullptr, 512, 512);

    // -- attention --
    ln_kernel<<<8192, 256>>>(r, ln1_g, ln1_b, nullptr, y_h, y_l, 512, 512);
    launch_gemm(y_h, y_l, qkvT_h, qkvT_l, bqkv, nullptr, nullptr, nullptr,
                nullptr, qkv_h, qkv_l, 8192, 1536, 512, 512, 512, 1536, 1.f, 0);
    vtrans_kernel<<<dim3(64, 2, 32), dim3(32, 8)>>>(qkv_h, qkv_l, vt_h, vt_l);
    {
        cudaFuncSetAttribute(flash_attn_kernel,
                             cudaFuncAttributeMaxDynamicSharedMemorySize, 163840);
        dim3 grid(16, 32);
        flash_attn_kernel<<<grid, 256, 163840>>>(qkv_h, qkv_l, vt_h, vt_l, o_h, o_l);
    }
    // r = r + o @ wo + bo
    launch_gemm(o_h, o_l, woT_h, woT_l, bo, r, nullptr, nullptr,
                r, nullptr, nullptr, 8192, 512, 512, 512, 512, 512, 1.f, 0);

    // -- FFN --
    ln_kernel<<<8192, 256>>>(r, ln2_g, ln2_b, nullptr, y_h, y_l, 512, 512);
    launch_gemm(y_h, y_l, ff1T_h, ff1T_l, ff1_b, nullptr, nullptr, nullptr,
                nullptr, ff_h, ff_l, 8192, 2048, 512, 512, 512, 2048, 1.f, 1);
    launch_gemm(ff_h, ff_l, ff2T_h, ff2T_l, ff2_b, r, nullptr, nullptr,
                r, nullptr, nullptr, 8192, 512, 2048, 2048, 2048, 512, 1.f, 0);

    // -- output projection + norm (reasoned also written into cat[:, 1024:2048]) --
    split_kernel<<<(int)(NTOK * RR / 4 / 256), 256>>>(r, rs_h, rs_l, NTOK * RR, 512, 512);
    launch_gemm(rs_h, rs_l, opT_h, opT_l, op_b, nullptr, nullptr, nullptr,
                tmpf, nullptr, nullptr, 8192, 1024, 512, 512, 512, 1024, 1.f, 0);
    ln_kernel<<<8192, 256>>>(tmpf, on_g, on_b, reason, cat_h + 1024, cat_l + 1024, 1024, 2048);

    // -- integration gate: single K=2048 GEMM over [hs | reasoned], relu fused --
    launch_gemm(cat_h, cat_l, g1T_h, g1T_l, gb1, nullptr, nullptr, nullptr,
                nullptr, t2_h, t2_l, 8192, 1024, 2048, 2048, 2048, 1024, 1.f, 1);
    // g2 + sigmoid + final blend fused: out = hs + sigmoid(.)*reason
    launch_gemm(t2_h, t2_l, g2T_h, g2T_l, gb2, nullptr, hs, reason,
                out, nullptr, nullptr, 8192, 1024, 1024, 1024, 1024, 1024, 1.f, 3);
}

// round 15
// speedup vs baseline: 2.1430x; 1.6728x over previous
#include <cuda_runtime.h>
#include <cuda_bf16.h>
#include <cstdint>
#include <math.h>

typedef __nv_bfloat16 bf;

// Problem constants
#define BB 4
#define SS 2048
#define HH 1024
#define RR 512
#define NHEAD 8
#define HDIM 64
#define NTOK 8192L   // B*S

// ===========================================================================
// Baseline-PTX helpers (sm_80-era: ldmatrix / mma.sync / cp.async)
// ===========================================================================
__device__ __forceinline__ uint32_t smem_to_u32(const void* p) {
    uint32_t a;
    asm("{ .reg .u64 t; cvta.to.shared.u64 t, %1; cvt.u32.u64 %0, t; }" : "=r"(a) : "l"(p));
    return a;
}
__device__ __forceinline__ void ldm_x4(uint32_t* r, uint32_t addr) {
    asm volatile("ldmatrix.sync.aligned.m8n8.x4.shared.b16 {%0,%1,%2,%3}, [%4];"
                 : "=r"(r[0]), "=r"(r[1]), "=r"(r[2]), "=r"(r[3]) : "r"(addr));
}
__device__ __forceinline__ void mma_bf16(float* d, const uint32_t* a, const uint32_t* b) {
    asm volatile("mma.sync.aligned.m16n8k16.row.col.f32.bf16.bf16.f32 "
                 "{%0,%1,%2,%3}, {%4,%5,%6,%7}, {%8,%9}, {%0,%1,%2,%3};"
                 : "+f"(d[0]), "+f"(d[1]), "+f"(d[2]), "+f"(d[3])
                 : "r"(a[0]), "r"(a[1]), "r"(a[2]), "r"(a[3]), "r"(b[0]), "r"(b[1]));
}
#define CP_ASYNC16(dst, src) \
    asm volatile("cp.async.cg.shared.global [%0], [%1], 16;" :: "r"(dst), "l"(src))
#define CP_COMMIT() asm volatile("cp.async.commit_group;" ::: "memory")
#define CP_WAIT1()  asm volatile("cp.async.wait_group 1;" ::: "memory")
#define CP_WAIT0()  asm volatile("cp.async.wait_group 0;" ::: "memory")

// Swizzled smem offset: rows of 64B (32 bf16), 4x 16B chunks, XOR by (row>>1)&3
#define SWZ(row, c) ((uint32_t)((row) * 64 + (((c) ^ (((row) >> 1) & 3)) << 4)))

// ===========================================================================
// Scratch (static device globals; no allocation allowed)
// ===========================================================================
__device__ float d_poolp[8 * BB * HH];
__device__ float d_pooled[BB * HH];
__device__ float d_h1[BB * 256];
__device__ float d_r[NTOK * RR];
__device__ float d_tmpf[NTOK * HH];
__device__ float d_reason[NTOK * HH];

__device__ bf d_cat_h[NTOK * 2 * HH], d_cat_l[NTOK * 2 * HH];   // [hs | reasoned]
__device__ bf d_y_h[NTOK * RR],   d_y_l[NTOK * RR];
__device__ bf d_qkv_h[NTOK * 3 * RR], d_qkv_l[NTOK * 3 * RR];
__device__ bf d_vt_h[(long)BB * NHEAD * HDIM * SS], d_vt_l[(long)BB * NHEAD * HDIM * SS];
__device__ bf d_o_h[NTOK * RR],   d_o_l[NTOK * RR];
__device__ bf d_ff_h[NTOK * 4 * RR], d_ff_l[NTOK * 4 * RR];
__device__ bf d_rs_h[NTOK * RR],  d_rs_l[NTOK * RR];
__device__ bf d_t2_h[NTOK * HH],  d_t2_l[NTOK * HH];
// transposed + split weights ([N,K] bf16)
__device__ bf d_rpT_h[RR * HH],       d_rpT_l[RR * HH];
__device__ bf d_qkvT_h[3 * RR * RR],  d_qkvT_l[3 * RR * RR];
__device__ bf d_woT_h[RR * RR],       d_woT_l[RR * RR];
__device__ bf d_ff1T_h[4 * RR * RR],  d_ff1T_l[4 * RR * RR];
__device__ bf d_ff2T_h[RR * 4 * RR],  d_ff2T_l[RR * 4 * RR];
__device__ bf d_opT_h[HH * RR],       d_opT_l[HH * RR];
__device__ bf d_g1T_h[HH * 2 * HH],   d_g1T_l[HH * 2 * HH];
__device__ bf d_g2T_h[HH * HH],       d_g2T_l[HH * HH];

// ===========================================================================
// Warp-MMA split-bf16 GEMM (proven core): D = Ah*Bh + Ah*Bl + Al*Bh
//   CTA tile 128 x 128, BK=32, 8 warps (2m x 4n), 2-stage, 2 CTAs/SM.
//   act: 0 none, 1 relu, 2 sigmoid, 3 fused gate: C = f1 + sigmoid(v)*f2
// ===========================================================================
__global__ void __launch_bounds__(256, 2) gemm_tc_kernel(
    const bf* __restrict__ Ah, const bf* __restrict__ Al,
    const bf* __restrict__ Bh, const bf* __restrict__ Bl,
    const float* __restrict__ bias, const float* __restrict__ res,
    const float* __restrict__ f1, const float* __restrict__ f2,
    float* __restrict__ C, bf* __restrict__ Ch, bf* __restrict__ Cl,
    int K, int lda, int ldb, int ldc,
    float alpha, int act)
{
    constexpr int BN  = 128;
    constexpr int ATB = 128 * 64;
    constexpr int BTB = BN * 64;
    constexpr int STG = 2 * ATB + 2 * BTB;

    extern __shared__ char smem[];
    uint32_t sb = smem_to_u32(smem);

    int tid = threadIdx.x, wid = tid >> 5, lane = tid & 31;
    int wm = wid & 1, wn = wid >> 1;

    int m0 = blockIdx.y * 128, n0 = blockIdx.x * BN;
    const bf* gAh = Ah + (long)m0 * lda;
    const bf* gAl = Al + (long)m0 * lda;
    const bf* gBh = Bh + (long)n0 * ldb;
    const bf* gBl = Bl + (long)n0 * ldb;

    const int nc = K >> 5;

    auto load_chunk = [&](int c, int s) {
        uint32_t base = sb + s * STG;
        long ko = (long)c << 5;
#pragma unroll
        for (int i = tid; i < 512; i += 256) {
            int r = i >> 2, q = i & 3;
            long go = (long)r * lda + ko + q * 8;
            uint32_t so = SWZ(r, q);
            CP_ASYNC16(base + so,       gAh + go);
            CP_ASYNC16(base + ATB + so, gAl + go);
        }
#pragma unroll
        for (int i = tid; i < 512; i += 256) {
            int r = i >> 2, q = i & 3;
            long go = (long)r * ldb + ko + q * 8;
            uint32_t so = SWZ(r, q);
            CP_ASYNC16(base + 2 * ATB + so,       gBh + go);
            CP_ASYNC16(base + 2 * ATB + BTB + so, gBl + go);
        }
    };

    float acc[4][4][4];
#pragma unroll
    for (int i = 0; i < 4; i++)
#pragma unroll
        for (int j = 0; j < 4; j++)
#pragma unroll
            for (int k = 0; k < 4; k++) acc[i][j][k] = 0.f;

    int a_row = lane & 15, a_ch = lane >> 4;
    int b_row = ((lane >> 4) << 3) + (lane & 7), b_ch = (lane >> 3) & 1;

    load_chunk(0, 0); CP_COMMIT();
    if (nc > 1) { load_chunk(1, 1); CP_COMMIT(); }

    for (int c = 0; c < nc; c++) {
        int s = c & 1;
        if (c + 1 < nc) CP_WAIT1(); else CP_WAIT0();
        __syncthreads();

        uint32_t sAh_ = sb + s * STG;
        uint32_t sAl_ = sAh_ + ATB;
        uint32_t sBh_ = sAh_ + 2 * ATB;
        uint32_t sBl_ = sBh_ + BTB;

#pragma unroll
        for (int kk = 0; kk < 2; kk++) {
            uint32_t ah[4][4], al_[4][4];
#pragma unroll
            for (int mt = 0; mt < 4; mt++) {
                uint32_t off = SWZ(wm * 64 + mt * 16 + a_row, 2 * kk + a_ch);
                ldm_x4(ah[mt],  sAh_ + off);
                ldm_x4(al_[mt], sAl_ + off);
            }
#pragma unroll
            for (int ntp = 0; ntp < 2; ntp++) {
                uint32_t boff = SWZ(wn * 32 + ntp * 16 + b_row, 2 * kk + b_ch);
                uint32_t bh[4], bl[4];
                ldm_x4(bh, sBh_ + boff);
                ldm_x4(bl, sBl_ + boff);
#pragma unroll
                for (int mt = 0; mt < 4; mt++) {
                    mma_bf16(acc[mt][2 * ntp],     ah[mt],  bh + 0);
                    mma_bf16(acc[mt][2 * ntp],     ah[mt],  bl + 0);
                    mma_bf16(acc[mt][2 * ntp],     al_[mt], bh + 0);
                    mma_bf16(acc[mt][2 * ntp + 1], ah[mt],  bh + 2);
                    mma_bf16(acc[mt][2 * ntp + 1], ah[mt],  bl + 2);
                    mma_bf16(acc[mt][2 * ntp + 1], al_[mt], bh + 2);
                }
            }
        }
        __syncthreads();
        if (c + 2 < nc) { load_chunk(c + 2, s); CP_COMMIT(); }
    }

    // Epilogue
    int mrow = lane >> 2, nc2 = (lane & 3) * 2;
#pragma unroll
    for (int mt = 0; mt < 4; mt++) {
#pragma unroll
        for (int nt = 0; nt < 4; nt++) {
#pragma unroll
            for (int e = 0; e < 4; e++) {
                int gr = m0 + wm * 64 + mt * 16 + mrow + ((e >> 1) << 3);
                int gn = n0 + wn * 32 + nt * 8 + nc2 + (e & 1);
                float v = acc[mt][nt][e] * alpha;
                if (bias) v += bias[gn];
                long off = (long)gr * ldc + gn;
                if (res) v += res[off];
                if (act == 1)      v = fmaxf(v, 0.f);
                else if (act == 2) v = 1.f / (1.f + __expf(-v));
                else if (act == 3) { v = 1.f / (1.f + __expf(-v)); v = f1[off] + v * f2[off]; }
                if (C) C[off] = v;
                if (Ch) {
                    bf h = __float2bfloat16(v);
                    Ch[off] = h;
                    Cl[off] = __float2bfloat16(v - __bfloat162float(h));
                }
            }
        }
    }
}

// ===========================================================================
// FlashAttention-2 (unchanged, proven): per (b,h,128-query tile)
// ===========================================================================
#define ADDR8(r, c)  ((uint32_t)((r) * 128 + (((c) ^ ((r) & 7)) << 4)))
#define ADDR16(r, c) ((uint32_t)((r) * 256 + ((((c) & 8) | (((c) & 7) ^ ((r) & 7))) << 4)))

__global__ void __launch_bounds__(256, 1) flash_attn_kernel(
    const bf* __restrict__ qkvh, const bf* __restrict__ qkvl,
    const bf* __restrict__ vth,  const bf* __restrict__ vtl,
    bf* __restrict__ oh, bf* __restrict__ ol)
{
    extern __shared__ char smem[];
    uint32_t sb = smem_to_u32(smem);
    const uint32_t QH = 0, QL = 16384, ST0 = 32768;

    int tid = threadIdx.x, wid = tid >> 5, lane = tid & 31;
    int z = blockIdx.y, b = z >> 3, hh = z & 7;
    int q0 = blockIdx.x * 128;

    const bf* gQh = qkvh + ((long)b * 2048 + q0) * 1536 + hh * 64;
    const bf* gQl = qkvl + ((long)b * 2048 + q0) * 1536 + hh * 64;
    const bf* gKh = qkvh + (long)b * 2048 * 1536 + 512 + hh * 64;
    const bf* gKl = qkvl + (long)b * 2048 * 1536 + 512 + hh * 64;
    const bf* gVh = vth + (long)z * 64 * 2048;
    const bf* gVl = vtl + (long)z * 64 * 2048;

    auto loadKV = [&](int j, int s) {
        uint32_t st = sb + ST0 + s * 65536;
#pragma unroll
        for (int i = tid; i < 1024; i += 256) {
            int r = i >> 3, c = i & 7;
            long go = (long)(j * 128 + r) * 1536 + c * 8;
            uint32_t so = ADDR8(r, c);
            CP_ASYNC16(st + so,         gKh + go);
            CP_ASYNC16(st + 16384 + so, gKl + go);
        }
#pragma unroll
        for (int i = tid; i < 1024; i += 256) {
            int r = i >> 4, c = i & 15;
            long go = (long)r * 2048 + j * 128 + c * 8;
            uint32_t so = ADDR16(r, c);
            CP_ASYNC16(st + 32768 + so, gVh + go);
            CP_ASYNC16(st + 49152 + so, gVl + go);
        }
    };

#pragma unroll
    for (int i = tid; i < 1024; i += 256) {
        int r = i >> 3, c = i & 7;
        long go = (long)r * 1536 + c * 8;
        uint32_t so = ADDR8(r, c);
        CP_ASYNC16(sb + QH + so, gQh + go);
        CP_ASYNC16(sb + QL + so, gQl + go);
    }
    loadKV(0, 0); CP_COMMIT();
    loadKV(1, 1); CP_COMMIT();

    int a_row = lane & 15, a_ch = lane >> 4;
    int b_row = ((lane >> 4) << 3) + (lane & 7), b_ch = (lane >> 3) & 1;

    uint32_t qh[4][4], ql[4][4];
    float accO[8][4];
#pragma unroll
    for (int i = 0; i < 8; i++)
#pragma unroll
        for (int e = 0; e < 4; e++) accO[i][e] = 0.f;
    float mrow[2] = {-1e30f, -1e30f}, lrow[2] = {0.f, 0.f};

    for (int j = 0; j < 16; j++) {
        if (j < 15) CP_WAIT1(); else CP_WAIT0();
        __syncthreads();
        if (j == 0) {
#pragma unroll
            for (int kk = 0; kk < 4; kk++) {
                uint32_t off = ADDR8(wid * 16 + a_row, 2 * kk + a_ch);
                ldm_x4(qh[kk], sb + QH + off);
                ldm_x4(ql[kk], sb + QL + off);
            }
        }
        uint32_t st = sb + ST0 + (j & 1) * 65536;

        float s[16][4];
#pragma unroll
        for (int i = 0; i < 16; i++)
#pragma unroll
            for (int e = 0; e < 4; e++) s[i][e] = 0.f;
#pragma unroll
        for (int kk = 0; kk < 4; kk++) {
#pragma unroll
            for (int ntp = 0; ntp < 8; ntp++) {
                uint32_t off = ADDR8(ntp * 16 + b_row, 2 * kk + b_ch);
                uint32_t bh[4], bl[4];
                ldm_x4(bh, st + off);
                ldm_x4(bl, st + 16384 + off);
                mma_bf16(s[2 * ntp],     qh[kk], bh + 0);
                mma_bf16(s[2 * ntp],     qh[kk], bl + 0);
                mma_bf16(s[2 * ntp],     ql[kk], bh + 0);
                mma_bf16(s[2 * ntp + 1], qh[kk], bh + 2);
                mma_bf16(s[2 * ntp + 1], qh[kk], bl + 2);
                mma_bf16(s[2 * ntp + 1], ql[kk], bh + 2);
            }
        }
#pragma unroll
        for (int i = 0; i < 16; i++)
#pragma unroll
            for (int e = 0; e < 4; e++) s[i][e] *= 0.125f;

#pragma unroll
        for (int h2 = 0; h2 < 2; h2++) {
            float vm = -1e30f;
#pragma unroll
            for (int nt = 0; nt < 16; nt++)
                vm = fmaxf(vm, fmaxf(s[nt][2 * h2], s[nt][2 * h2 + 1]));
            vm = fmaxf(vm, __shfl_xor_sync(0xffffffffu, vm, 1));
            vm = fmaxf(vm, __shfl_xor_sync(0xffffffffu, vm, 2));
            float mn = fmaxf(mrow[h2], vm);
            float scale = __expf(mrow[h2] - mn);
            mrow[h2] = mn;
            float ps = 0.f;
#pragma unroll
            for (int nt = 0; nt < 16; nt++) {
                float e0 = __expf(s[nt][2 * h2] - mn);
                float e1 = __expf(s[nt][2 * h2 + 1] - mn);
                s[nt][2 * h2] = e0; s[nt][2 * h2 + 1] = e1;
                ps += e0 + e1;
            }
            ps += __shfl_xor_sync(0xffffffffu, ps, 1);
            ps += __shfl_xor_sync(0xffffffffu, ps, 2);
            lrow[h2] = lrow[h2] * scale + ps;
#pragma unroll
            for (int nt2 = 0; nt2 < 8; nt2++) {
                accO[nt2][2 * h2]     *= scale;
                accO[nt2][2 * h2 + 1] *= scale;
            }
        }

#pragma unroll
        for (int kt = 0; kt < 8; kt++) {
            uint32_t Ph[4], Pl[4];
#pragma unroll
            for (int jj = 0; jj < 4; jj++) {
                float va = s[2 * kt + (jj >> 1)][(jj & 1) * 2];
                float vb = s[2 * kt + (jj >> 1)][(jj & 1) * 2 + 1];
                bf ha = __float2bfloat16(va), hb = __float2bfloat16(vb);
                float ra = va - __bfloat162float(ha), rb = vb - __bfloat162float(hb);
                Ph[jj] = (uint32_t)__bfloat16_as_ushort(ha) |
                         ((uint32_t)__bfloat16_as_ushort(hb) << 16);
                Pl[jj] = (uint32_t)__bfloat16_as_ushort(__float2bfloat16(ra)) |
                         ((uint32_t)__bfloat16_as_ushort(__float2bfloat16(rb)) << 16);
            }
#pragma unroll
            for (int np = 0; np < 4; np++) {
                uint32_t off = ADDR16(np * 16 + b_row, 2 * kt + b_ch);
                uint32_t vh[4], vl[4];
                ldm_x4(vh, st + 32768 + off);
                ldm_x4(vl, st + 49152 + off);
                mma_bf16(accO[2 * np],     Ph, vh + 0);
                mma_bf16(accO[2 * np],     Ph, vl + 0);
                mma_bf16(accO[2 * np],     Pl, vh + 0);
                mma_bf16(accO[2 * np + 1], Ph, vh + 2);
                mma_bf16(accO[2 * np + 1], Ph, vl + 2);
                mma_bf16(accO[2 * np + 1], Pl, vh + 2);
            }
        }
        __syncthreads();
        if (j + 2 < 16) { loadKV(j + 2, j & 1); CP_COMMIT(); }
    }

    float inv0 = 1.f / lrow[0], inv1 = 1.f / lrow[1];
    long tok0 = (long)b * 2048 + q0 + wid * 16 + (lane >> 2);
    int colb = hh * 64 + (lane & 3) * 2;
#pragma unroll
    for (int nt2 = 0; nt2 < 8; nt2++) {
#pragma unroll
        for (int e = 0; e < 4; e++) {
            long row = tok0 + 8 * (e >> 1);
            int col = colb + nt2 * 8 + (e & 1);
            float v = accO[nt2][e] * ((e >> 1) ? inv1 : inv0);
            bf h = __float2bfloat16(v);
            long off = row * 512 + col;
            oh[off] = h;
            ol[off] = __float2bfloat16(v - __bfloat162float(h));
        }
    }
}

// ===========================================================================
// Aux kernels (this round: warp-per-row LN, vectorized split, parallel CA)
// ===========================================================================

// LayerNorm, one warp per row. grid = rows/8, block 256.
template <int D>
__global__ void ln_kernel(const float* __restrict__ x, const float* __restrict__ g,
                          const float* __restrict__ b, float* __restrict__ yf,
                          bf* __restrict__ yh, bf* __restrict__ yl, int ldy)
{
    constexpr int NP = D / 128;          // float4 passes per lane (4 or 8)
    int wid = threadIdx.x >> 5, lane = threadIdx.x & 31;
    long row = (long)blockIdx.x * 8 + wid;
    const float* xr = x + row * D;

    float v[NP * 4];
    float s = 0.f;
#pragma unroll
    for (int p = 0; p < NP; p++) {
        float4 t = *(const float4*)(xr + p * 128 + lane * 4);
        v[4 * p] = t.x; v[4 * p + 1] = t.y; v[4 * p + 2] = t.z; v[4 * p + 3] = t.w;
        s += (t.x + t.y) + (t.z + t.w);
    }
#pragma unroll
    for (int o = 16; o; o >>= 1) s += __shfl_xor_sync(0xffffffffu, s, o);
    float mean = s * (1.f / D);
    float vs = 0.f;
#pragma unroll
    for (int i = 0; i < NP * 4; i++) { float d = v[i] - mean; vs += d * d; }
#pragma unroll
    for (int o = 16; o; o >>= 1) vs += __shfl_xor_sync(0xffffffffu, vs, o);
    float rstd = rsqrtf(vs * (1.f / D) + 1e-5f);

#pragma unroll
    for (int p = 0; p < NP; p++) {
        int idx = p * 128 + lane * 4;
        float4 gg = *(const float4*)(g + idx);
        float4 bb = *(const float4*)(b + idx);
        float o0 = (v[4 * p]     - mean) * rstd * gg.x + bb.x;
        float o1 = (v[4 * p + 1] - mean) * rstd * gg.y + bb.y;
        float o2 = (v[4 * p + 2] - mean) * rstd * gg.z + bb.z;
        float o3 = (v[4 * p + 3] - mean) * rstd * gg.w + bb.w;
        if (yf) {
            float4 t = {o0, o1, o2, o3};
            *(float4*)(yf + row * D + idx) = t;
        }
        if (yh) {
            long off = row * (long)ldy + idx;
            bf h0 = __float2bfloat16(o0), h1 = __float2bfloat16(o1);
            bf h2 = __float2bfloat16(o2), h3 = __float2bfloat16(o3);
            uint32_t hp0 = (uint32_t)__bfloat16_as_ushort(h0) |
                           ((uint32_t)__bfloat16_as_ushort(h1) << 16);
            uint32_t hp1 = (uint32_t)__bfloat16_as_ushort(h2) |
                           ((uint32_t)__bfloat16_as_ushort(h3) << 16);
            *(uint2*)(yh + off) = make_uint2(hp0, hp1);
            bf l0 = __float2bfloat16(o0 - __bfloat162float(h0));
            bf l1 = __float2bfloat16(o1 - __bfloat162float(h1));
            bf l2 = __float2bfloat16(o2 - __bfloat162float(h2));
            bf l3 = __float2bfloat16(o3 - __bfloat162float(h3));
            uint32_t lp0 = (uint32_t)__bfloat16_as_ushort(l0) |
                           ((uint32_t)__bfloat16_as_ushort(l1) << 16);
            uint32_t lp1 = (uint32_t)__bfloat16_as_ushort(l2) |
                           ((uint32_t)__bfloat16_as_ushort(l3) << 16);
            *(uint2*)(yl + off) = make_uint2(lp0, lp1);
        }
    }
}

// fp32 -> split bf16, 8 elems/thread, uint4 stores
__global__ void split_kernel(const float* __restrict__ x, bf* __restrict__ h,
                             bf* __restrict__ l, long n, int rowlen, int ldo)
{
    long i = ((long)blockIdx.x * 256 + threadIdx.x) * 8;
    if (i < n) {
        float4 v0 = *(const float4*)(x + i);
        float4 v1 = *(const float4*)(x + i + 4);
        float a[8] = {v0.x, v0.y, v0.z, v0.w, v1.x, v1.y, v1.z, v1.w};
        uint32_t hp[4], lp[4];
#pragma unroll
        for (int j = 0; j < 4; j++) {
            bf h0 = __float2bfloat16(a[2 * j]);
            bf h1 = __float2bfloat16(a[2 * j + 1]);
            hp[j] = (uint32_t)__bfloat16_as_ushort(h0) |
                    ((uint32_t)__bfloat16_as_ushort(h1) << 16);
            bf l0 = __float2bfloat16(a[2 * j] - __bfloat162float(h0));
            bf l1 = __float2bfloat16(a[2 * j + 1] - __bfloat162float(h1));
            lp[j] = (uint32_t)__bfloat16_as_ushort(l0) |
                    ((uint32_t)__bfloat16_as_ushort(l1) << 16);
        }
        long off = (i / rowlen) * (long)ldo + (i % rowlen);
        *(uint4*)(h + off) = make_uint4(hp[0], hp[1], hp[2], hp[3]);
        *(uint4*)(l + off) = make_uint4(lp[0], lp[1], lp[2], lp[3]);
    }
}

// All weight transposes + splits in ONE launch. W[K,N] fp32 -> Th/Tl [N,K] bf16.
struct WTDesc { const float* W; bf* Th; bf* Tl; int K; int N; int cum; };
struct WTArgs { WTDesc m[8]; };

__global__ void wtrans_all_kernel(WTArgs args)
{
    __shared__ float t[32][33];
    int bid = blockIdx.x;
    int mi = 0;
#pragma unroll
    for (int i = 0; i < 8; i++)
        if (bid >= args.m[i].cum) mi = i + 1;
    const WTDesc& d = args.m[mi];
    int local = bid - (mi ? args.m[mi - 1].cum : 0);
    int ktiles = d.K >> 5;
    int k0 = (local % ktiles) * 32, n0 = (local / ktiles) * 32;

    int x = threadIdx.x, y = threadIdx.y;   // 32 x 8
#pragma unroll
    for (int i = 0; i < 32; i += 8)
        t[y + i][x] = d.W[(long)(k0 + y + i) * d.N + n0 + x];
    __syncthreads();
#pragma unroll
    for (int i = 0; i < 32; i += 8) {
        float v = t[x][y + i];
        bf h = __float2bfloat16(v);
        long o = (long)(n0 + y + i) * d.K + k0 + x;
        d.Th[o] = h;
        d.Tl[o] = __float2bfloat16(v - __bfloat162float(h));
    }
}

// V transpose (bf16): qkv[:,1024+h*64 : +64] -> vt[z][64][2048]
__global__ void vtrans_kernel(const bf* __restrict__ qh, const bf* __restrict__ ql,
                              bf* __restrict__ vh, bf* __restrict__ vl)
{
    __shared__ bf th[32][33], tl[32][33];
    int z = blockIdx.z; int b = z >> 3, hh = z & 7;
    int k0 = blockIdx.x * 32, n0 = blockIdx.y * 32;
    int x = threadIdx.x, y = threadIdx.y;
    const long ibase = (long)b * 2048 * 1536 + 1024 + hh * 64;
#pragma unroll
    for (int i = 0; i < 32; i += 8) {
        long go = ibase + (long)(k0 + y + i) * 1536 + n0 + x;
        th[y + i][x] = qh[go];
        tl[y + i][x] = ql[go];
    }
    __syncthreads();
    const long obase = (long)z * 64 * 2048;
#pragma unroll
    for (int i = 0; i < 32; i += 8) {
        long o = obase + (long)(n0 + y + i) * 2048 + k0 + x;
        vh[o] = th[x][y + i];
        vl[o] = tl[x][y + i];
    }
}

// Pool phase 1: partial[z][b][h] = sum over s in [z*256,(z+1)*256)
__global__ void pool_partial_kernel(const float* __restrict__ hs, float* __restrict__ part)
{
    int b = blockIdx.y, z = blockIdx.z;
    int h = blockIdx.x * 256 + threadIdx.x;
    const float* p = hs + (long)b * SS * HH + (long)z * 256 * HH + h;
    float sum = 0.f;
#pragma unroll 8
    for (int s = 0; s < 256; s++) sum += p[(long)s * HH];
    part[((long)z * BB + b) * HH + h] = sum;
}

// Pool phase 2: pooled[b][h] = (sum of 8 partials) / 2048
__global__ void pool_reduce_kernel(const float* __restrict__ part, float* __restrict__ pooled)
{
    int b = blockIdx.y;
    int h = blockIdx.x * 256 + threadIdx.x;
    float sum = 0.f;
#pragma unroll
    for (int z = 0; z < 8; z++) sum += part[((long)z * BB + b) * HH + h];
    pooled[b * HH + h] = sum * (1.f / SS);
}

// CA layer 1 (parallel): h1[b][col] = relu(pooled[b] . w1[:,col] + b1[col])
__global__ void ca1_kernel(const float* __restrict__ pooled,
                           const float* __restrict__ w1, const float* __restrict__ b1,
                           float* __restrict__ h1)
{
    int b = blockIdx.x, grp = blockIdx.y;
    int col = grp * 32 + threadIdx.x;
    float acc = b1[col];
    const float* pr = pooled + b * HH;
    for (int k = 0; k < HH; k++)
        acc = fmaf(pr[k], w1[k * 256 + col], acc);
    h1[b * 256 + col] = fmaxf(acc, 0.f);
}

// CA layers 2+3 (tiny, 1 block of 32)
__global__ void ca2_kernel(const float* __restrict__ h1,
                           const float* __restrict__ w2, const float* __restrict__ b2,
                           const float* __restrict__ w3, const float* __restrict__ b3,
                           float* __restrict__ scores_out)
{
    __shared__ float h2[BB][32];
    int t = threadIdx.x;
    for (int b = 0; b < BB; b++) {
        float acc = b2[t];
        for (int k = 0; k < 256; k++)
            acc = fmaf(h1[b * 256 + k], w2[k * 32 + t], acc);
        h2[b][t] = fmaxf(acc, 0.f);
    }
    __syncwarp();
    if (t < BB) {
        float acc = b3[0];
        for (int k = 0; k < 32; k++) acc = fmaf(h2[t][k], w3[k], acc);
        scores_out[t] = 1.f / (1.f + expf(-acc));
    }
}

// ===========================================================================
// Host
// ===========================================================================
static void launch_gemm(const bf* Ah, const bf* Al, const bf* Bh, const bf* Bl,
                        const float* bias, const float* res,
                        const float* f1, const float* f2,
                        float* C, bf* Ch, bf* Cl,
                        int M, int N, int K, int lda, int ldb, int ldc,
                        float alpha, int act)
{
    int sm = 2 * (2 * 128 * 64 + 2 * 128 * 64);   // 65536
    cudaFuncSetAttribute(gemm_tc_kernel, cudaFuncAttributeMaxDynamicSharedMemorySize, sm);
    dim3 grid(N / 128, M / 128, 1);
    gemm_tc_kernel<<<grid, 256, sm>>>(Ah, Al, Bh, Bl, bias, res, f1, f2, C, Ch, Cl,
        K, lda, ldb, ldc, alpha, act);
}

#define SYM(p, s) do { void* _t; cudaGetSymbolAddress(&_t, s); p = (decltype(p))_t; } while (0)

extern "C" void kernel_launch(void* const* d_in, const int* in_sizes, int n_in,
                              void* d_out, int out_size)
{
    const float* hs    = (const float*)d_in[0];
    const float* ca_w1 = (const float*)d_in[1];
    const float* ca_b1 = (const float*)d_in[2];
    const float* ca_w2 = (const float*)d_in[3];
    const float* ca_b2 = (const float*)d_in[4];
    const float* ca_w3 = (const float*)d_in[5];
    const float* ca_b3 = (const float*)d_in[6];
    const float* rp_w  = (const float*)d_in[7];
    const float* rp_b  = (const float*)d_in[8];
    const float* rn_g  = (const float*)d_in[9];
    const float* rn_b  = (const float*)d_in[10];
    const float* ln1_g = (const float*)d_in[11];
    const float* ln1_b = (const float*)d_in[12];
    const float* wqkv  = (const float*)d_in[13];
    const float* bqkv  = (const float*)d_in[14];
    const float* wo    = (const float*)d_in[15];
    const float* bo    = (const float*)d_in[16];
    const float* ln2_g = (const float*)d_in[17];
    const float* ln2_b = (const float*)d_in[18];
    const float* ff1_w = (const float*)d_in[19];
    const float* ff1_b = (const float*)d_in[20];
    const float* ff2_w = (const float*)d_in[21];
    const float* ff2_b = (const float*)d_in[22];
    const float* op_w  = (const float*)d_in[23];
    const float* op_b  = (const float*)d_in[24];
    const float* on_g  = (const float*)d_in[25];
    const float* on_b  = (const float*)d_in[26];
    const float* gw1   = (const float*)d_in[27];
    const float* gb1   = (const float*)d_in[28];
    const float* gw2   = (const float*)d_in[29];
    const float* gb2   = (const float*)d_in[30];

    float* out = (float*)d_out;
    float* cs  = out + NTOK * HH;

    float *poolp, *pooled, *h1f, *r, *tmpf, *reason;
    SYM(poolp, d_poolp); SYM(pooled, d_pooled); SYM(h1f, d_h1);
    SYM(r, d_r); SYM(tmpf, d_tmpf); SYM(reason, d_reason);
    bf *cat_h, *cat_l, *y_h, *y_l, *qkv_h, *qkv_l, *vt_h, *vt_l;
    bf *o_h, *o_l, *ff_h, *ff_l, *rs_h, *rs_l, *t2_h, *t2_l;
    SYM(cat_h, d_cat_h); SYM(cat_l, d_cat_l); SYM(y_h, d_y_h); SYM(y_l, d_y_l);
    SYM(qkv_h, d_qkv_h); SYM(qkv_l, d_qkv_l);
    SYM(vt_h, d_vt_h); SYM(vt_l, d_vt_l);
    SYM(o_h, d_o_h); SYM(o_l, d_o_l); SYM(ff_h, d_ff_h); SYM(ff_l, d_ff_l);
    SYM(rs_h, d_rs_h); SYM(rs_l, d_rs_l);
    SYM(t2_h, d_t2_h); SYM(t2_l, d_t2_l);
    bf *rpT_h, *rpT_l, *qkvT_h, *qkvT_l, *woT_h, *woT_l, *ff1T_h, *ff1T_l;
    bf *ff2T_h, *ff2T_l, *opT_h, *opT_l, *g1T_h, *g1T_l, *g2T_h, *g2T_l;
    SYM(rpT_h, d_rpT_h); SYM(rpT_l, d_rpT_l); SYM(qkvT_h, d_qkvT_h); SYM(qkvT_l, d_qkvT_l);
    SYM(woT_h, d_woT_h); SYM(woT_l, d_woT_l); SYM(ff1T_h, d_ff1T_h); SYM(ff1T_l, d_ff1T_l);
    SYM(ff2T_h, d_ff2T_h); SYM(ff2T_l, d_ff2T_l); SYM(opT_h, d_opT_h); SYM(opT_l, d_opT_l);
    SYM(g1T_h, d_g1T_h); SYM(g1T_l, d_g1T_l); SYM(g2T_h, d_g2T_h); SYM(g2T_l, d_g2T_l);

    // -- all weight transposes + splits in one launch --
    {
        WTArgs wa;
        WTDesc ds[8] = {
            {rp_w,  rpT_h,  rpT_l,  1024, 512,  0},
            {wqkv,  qkvT_h, qkvT_l, 512,  1536, 0},
            {wo,    woT_h,  woT_l,  512,  512,  0},
            {ff1_w, ff1T_h, ff1T_l, 512,  2048, 0},
            {ff2_w, ff2T_h, ff2T_l, 2048, 512,  0},
            {op_w,  opT_h,  opT_l,  512,  1024, 0},
            {gw1,   g1T_h,  g1T_l,  2048, 1024, 0},
            {gw2,   g2T_h,  g2T_l,  1024, 1024, 0},
        };
        int cum = 0;
        for (int i = 0; i < 8; i++) {
            cum += (ds[i].K >> 5) * (ds[i].N >> 5);
            ds[i].cum = cum;
            wa.m[i] = ds[i];
        }
        wtrans_all_kernel<<<cum, dim3(32, 8)>>>(wa);
    }

    // -- complexity assessor (parallelized) --
    pool_partial_kernel<<<dim3(HH / 256, BB, 8), 256>>>(hs, poolp);
    pool_reduce_kernel<<<dim3(HH / 256, BB), 256>>>(poolp, pooled);
    ca1_kernel<<<dim3(BB, 8), 32>>>(pooled, ca_w1, ca_b1, h1f);
    ca2_kernel<<<1, 32>>>(h1f, ca_w2, ca_b2, ca_w3, ca_b3, cs);

    // -- split hidden states into cat[:, 0:1024] --
    split_kernel<<<(int)(NTOK * HH / 8 / 256), 256>>>(hs, cat_h, cat_l, NTOK * HH, 1024, 2048);

    // -- reasoning proj + pre-norm --
    launch_gemm(cat_h, cat_l, rpT_h, rpT_l, rp_b, nullptr, nullptr, nullptr,
                r, nullptr, nullptr, 8192, 512, 1024, 2048, 1024, 512, 1.f, 0);
    ln_kernel<512><<<1024, 256>>>(r, rn_g, rn_b, r, nullptr, nullptr, 512);

    // -- attention --
    ln_kernel<512><<<1024, 256>>>(r, ln1_g, ln1_b, nullptr, y_h, y_l, 512);
    launch_gemm(y_h, y_l, qkvT_h, qkvT_l, bqkv, nullptr, nullptr, nullptr,
                nullptr, qkv_h, qkv_l, 8192, 1536, 512, 512, 512, 1536, 1.f, 0);
    vtrans_kernel<<<dim3(64, 2, 32), dim3(32, 8)>>>(qkv_h, qkv_l, vt_h, vt_l);
    {
        cudaFuncSetAttribute(flash_attn_kernel,
                             cudaFuncAttributeMaxDynamicSharedMemorySize, 163840);
        dim3 grid(16, 32);
        flash_attn_kernel<<<grid, 256, 163840>>>(qkv_h, qkv_l, vt_h, vt_l, o_h, o_l);
    }
    // r = r + o @ wo + bo
    launch_gemm(o_h, o_l, woT_h, woT_l, bo, r, nullptr, nullptr,
                r, nullptr, nullptr, 8192, 512, 512, 512, 512, 512, 1.f, 0);

    // -- FFN --
    ln_kernel<512><<<1024, 256>>>(r, ln2_g, ln2_b, nullptr, y_h, y_l, 512);
    launch_gemm(y_h, y_l, ff1T_h, ff1T_l, ff1_b, nullptr, nullptr, nullptr,
                nullptr, ff_h, ff_l, 8192, 2048, 512, 512, 512, 2048, 1.f, 1);
    launch_gemm(ff_h, ff_l, ff2T_h, ff2T_l, ff2_b, r, nullptr, nullptr,
                r, nullptr, nullptr, 8192, 512, 2048, 2048, 2048, 512, 1.f, 0);

    // -- output projection + norm (reasoned also written into cat[:, 1024:2048]) --
    split_kernel<<<(int)(NTOK * RR / 8 / 256), 256>>>(r, rs_h, rs_l, NTOK * RR, 512, 512);
    launch_gemm(rs_h, rs_l, opT_h, opT_l, op_b, nullptr, nullptr, nullptr,
                tmpf, nullptr, nullptr, 8192, 1024, 512, 512, 512, 1024, 1.f, 0);
    ln_kernel<1024><<<1024, 256>>>(tmpf, on_g, on_b, reason, cat_h + 1024, cat_l + 1024, 2048);

    // -- integration gate: single K=2048 GEMM over [hs | reasoned], relu fused --
    launch_gemm(cat_h, cat_l, g1T_h, g1T_l, gb1, nullptr, nullptr, nullptr,
                nullptr, t2_h, t2_l, 8192, 1024, 2048, 2048, 2048, 1024, 1.f, 1);
    // g2 + sigmoid + final blend fused: out = hs + sigmoid(.)*reason
    launch_gemm(t2_h, t2_l, g2T_h, g2T_l, gb2, nullptr, hs, reason,
                out, nullptr, nullptr, 8192, 1024, 1024, 1024, 1024, 1024, 1.f, 3);
}

// round 16
// speedup vs baseline: 2.2538x; 1.0517x over previous
#include <cuda_runtime.h>
#include <cuda_bf16.h>
#include <cstdint>
#include <math.h>

typedef __nv_bfloat16 bf;

// Problem constants
#define BB 4
#define SS 2048
#define HH 1024
#define RR 512
#define NHEAD 8
#define HDIM 64
#define NTOK 8192L   // B*S

// ===========================================================================
// Baseline-PTX helpers (sm_80-era: ldmatrix / mma.sync / cp.async)
// ===========================================================================
__device__ __forceinline__ uint32_t smem_to_u32(const void* p) {
    uint32_t a;
    asm("{ .reg .u64 t; cvta.to.shared.u64 t, %1; cvt.u32.u64 %0, t; }" : "=r"(a) : "l"(p));
    return a;
}
__device__ __forceinline__ void ldm_x4(uint32_t* r, uint32_t addr) {
    asm volatile("ldmatrix.sync.aligned.m8n8.x4.shared.b16 {%0,%1,%2,%3}, [%4];"
                 : "=r"(r[0]), "=r"(r[1]), "=r"(r[2]), "=r"(r[3]) : "r"(addr));
}
__device__ __forceinline__ void mma_bf16(float* d, const uint32_t* a, const uint32_t* b) {
    asm volatile("mma.sync.aligned.m16n8k16.row.col.f32.bf16.bf16.f32 "
                 "{%0,%1,%2,%3}, {%4,%5,%6,%7}, {%8,%9}, {%0,%1,%2,%3};"
                 : "+f"(d[0]), "+f"(d[1]), "+f"(d[2]), "+f"(d[3])
                 : "r"(a[0]), "r"(a[1]), "r"(a[2]), "r"(a[3]), "r"(b[0]), "r"(b[1]));
}
#define CP_ASYNC16(dst, src) \
    asm volatile("cp.async.cg.shared.global [%0], [%1], 16;" :: "r"(dst), "l"(src))
#define CP_COMMIT() asm volatile("cp.async.commit_group;" ::: "memory")
#define CP_WAIT1()  asm volatile("cp.async.wait_group 1;" ::: "memory")
#define CP_WAIT0()  asm volatile("cp.async.wait_group 0;" ::: "memory")

// Swizzled smem offset: rows of 64B (32 bf16), 4x 16B chunks, XOR by (row>>1)&3
#define SWZ(row, c) ((uint32_t)((row) * 64 + (((c) ^ (((row) >> 1) & 3)) << 4)))

// ===========================================================================
// Scratch (static device globals; no allocation allowed)
// ===========================================================================
__device__ float d_poolp[8 * BB * HH];
__device__ float d_pooled[BB * HH];
__device__ float d_h1p[8 * BB * 256];
__device__ float d_r[NTOK * RR];
__device__ float d_tmpf[NTOK * HH];
__device__ float d_reason[NTOK * HH];

__device__ bf d_cat_h[NTOK * 2 * HH], d_cat_l[NTOK * 2 * HH];   // [hs | reasoned]
__device__ bf d_y_h[NTOK * RR],   d_y_l[NTOK * RR];
__device__ bf d_qkv_h[NTOK * 3 * RR], d_qkv_l[NTOK * 3 * RR];
__device__ bf d_vt_h[(long)BB * NHEAD * HDIM * SS], d_vt_l[(long)BB * NHEAD * HDIM * SS];
__device__ bf d_o_h[NTOK * RR],   d_o_l[NTOK * RR];
__device__ bf d_ff_h[NTOK * 4 * RR], d_ff_l[NTOK * 4 * RR];
__device__ bf d_rs_h[NTOK * RR],  d_rs_l[NTOK * RR];
__device__ bf d_t2_h[NTOK * HH],  d_t2_l[NTOK * HH];
// transposed + split weights ([N,K] bf16)
__device__ bf d_rpT_h[RR * HH],       d_rpT_l[RR * HH];
__device__ bf d_qkvT_h[3 * RR * RR],  d_qkvT_l[3 * RR * RR];
__device__ bf d_woT_h[RR * RR],       d_woT_l[RR * RR];
__device__ bf d_ff1T_h[4 * RR * RR],  d_ff1T_l[4 * RR * RR];
__device__ bf d_ff2T_h[RR * 4 * RR],  d_ff2T_l[RR * 4 * RR];
__device__ bf d_opT_h[HH * RR],       d_opT_l[HH * RR];
__device__ bf d_g1T_h[HH * 2 * HH],   d_g1T_l[HH * 2 * HH];
__device__ bf d_g2T_h[HH * HH],       d_g2T_l[HH * HH];

// ===========================================================================
// Warp-MMA split-bf16 GEMM (proven core): D = Ah*Bh + Ah*Bl + Al*Bh
//   CTA tile 128 x 128, BK=32, 8 warps (2m x 4n), 2-stage, 2 CTAs/SM.
//   act: 0 none, 1 relu, 2 sigmoid, 3 fused gate: C = f1 + sigmoid(v)*f2
// ===========================================================================
__global__ void __launch_bounds__(256, 2) gemm_tc_kernel(
    const bf* __restrict__ Ah, const bf* __restrict__ Al,
    const bf* __restrict__ Bh, const bf* __restrict__ Bl,
    const float* __restrict__ bias, const float* __restrict__ res,
    const float* __restrict__ f1, const float* __restrict__ f2,
    float* __restrict__ C, bf* __restrict__ Ch, bf* __restrict__ Cl,
    int K, int lda, int ldb, int ldc,
    float alpha, int act)
{
    constexpr int BN  = 128;
    constexpr int ATB = 128 * 64;
    constexpr int BTB = BN * 64;
    constexpr int STG = 2 * ATB + 2 * BTB;

    extern __shared__ char smem[];
    uint32_t sb = smem_to_u32(smem);

    int tid = threadIdx.x, wid = tid >> 5, lane = tid & 31;
    int wm = wid & 1, wn = wid >> 1;

    int m0 = blockIdx.y * 128, n0 = blockIdx.x * BN;
    const bf* gAh = Ah + (long)m0 * lda;
    const bf* gAl = Al + (long)m0 * lda;
    const bf* gBh = Bh + (long)n0 * ldb;
    const bf* gBl = Bl + (long)n0 * ldb;

    const int nc = K >> 5;

    auto load_chunk = [&](int c, int s) {
        uint32_t base = sb + s * STG;
        long ko = (long)c << 5;
#pragma unroll
        for (int i = tid; i < 512; i += 256) {
            int r = i >> 2, q = i & 3;
            long go = (long)r * lda + ko + q * 8;
            uint32_t so = SWZ(r, q);
            CP_ASYNC16(base + so,       gAh + go);
            CP_ASYNC16(base + ATB + so, gAl + go);
        }
#pragma unroll
        for (int i = tid; i < 512; i += 256) {
            int r = i >> 2, q = i & 3;
            long go = (long)r * ldb + ko + q * 8;
            uint32_t so = SWZ(r, q);
            CP_ASYNC16(base + 2 * ATB + so,       gBh + go);
            CP_ASYNC16(base + 2 * ATB + BTB + so, gBl + go);
        }
    };

    float acc[4][4][4];
#pragma unroll
    for (int i = 0; i < 4; i++)
#pragma unroll
        for (int j = 0; j < 4; j++)
#pragma unroll
            for (int k = 0; k < 4; k++) acc[i][j][k] = 0.f;

    int a_row = lane & 15, a_ch = lane >> 4;
    int b_row = ((lane >> 4) << 3) + (lane & 7), b_ch = (lane >> 3) & 1;

    load_chunk(0, 0); CP_COMMIT();
    if (nc > 1) { load_chunk(1, 1); CP_COMMIT(); }

    for (int c = 0; c < nc; c++) {
        int s = c & 1;
        if (c + 1 < nc) CP_WAIT1(); else CP_WAIT0();
        __syncthreads();

        uint32_t sAh_ = sb + s * STG;
        uint32_t sAl_ = sAh_ + ATB;
        uint32_t sBh_ = sAh_ + 2 * ATB;
        uint32_t sBl_ = sBh_ + BTB;

#pragma unroll
        for (int kk = 0; kk < 2; kk++) {
            uint32_t ah[4][4], al_[4][4];
#pragma unroll
            for (int mt = 0; mt < 4; mt++) {
                uint32_t off = SWZ(wm * 64 + mt * 16 + a_row, 2 * kk + a_ch);
                ldm_x4(ah[mt],  sAh_ + off);
                ldm_x4(al_[mt], sAl_ + off);
            }
#pragma unroll
            for (int ntp = 0; ntp < 2; ntp++) {
                uint32_t boff = SWZ(wn * 32 + ntp * 16 + b_row, 2 * kk + b_ch);
                uint32_t bh[4], bl[4];
                ldm_x4(bh, sBh_ + boff);
                ldm_x4(bl, sBl_ + boff);
#pragma unroll
                for (int mt = 0; mt < 4; mt++) {
                    mma_bf16(acc[mt][2 * ntp],     ah[mt],  bh + 0);
                    mma_bf16(acc[mt][2 * ntp],     ah[mt],  bl + 0);
                    mma_bf16(acc[mt][2 * ntp],     al_[mt], bh + 0);
                    mma_bf16(acc[mt][2 * ntp + 1], ah[mt],  bh + 2);
                    mma_bf16(acc[mt][2 * ntp + 1], ah[mt],  bl + 2);
                    mma_bf16(acc[mt][2 * ntp + 1], al_[mt], bh + 2);
                }
            }
        }
        __syncthreads();
        if (c + 2 < nc) { load_chunk(c + 2, s); CP_COMMIT(); }
    }

    // Epilogue
    int mrow = lane >> 2, nc2 = (lane & 3) * 2;
#pragma unroll
    for (int mt = 0; mt < 4; mt++) {
#pragma unroll
        for (int nt = 0; nt < 4; nt++) {
#pragma unroll
            for (int e = 0; e < 4; e++) {
                int gr = m0 + wm * 64 + mt * 16 + mrow + ((e >> 1) << 3);
                int gn = n0 + wn * 32 + nt * 8 + nc2 + (e & 1);
                float v = acc[mt][nt][e] * alpha;
                if (bias) v += bias[gn];
                long off = (long)gr * ldc + gn;
                if (res) v += res[off];
                if (act == 1)      v = fmaxf(v, 0.f);
                else if (act == 2) v = 1.f / (1.f + __expf(-v));
                else if (act == 3) { v = 1.f / (1.f + __expf(-v)); v = f1[off] + v * f2[off]; }
                if (C) C[off] = v;
                if (Ch) {
                    bf h = __float2bfloat16(v);
                    Ch[off] = h;
                    Cl[off] = __float2bfloat16(v - __bfloat162float(h));
                }
            }
        }
    }
}

// ===========================================================================
// FlashAttention-2 (unchanged, proven): per (b,h,128-query tile)
// ===========================================================================
#define ADDR8(r, c)  ((uint32_t)((r) * 128 + (((c) ^ ((r) & 7)) << 4)))
#define ADDR16(r, c) ((uint32_t)((r) * 256 + ((((c) & 8) | (((c) & 7) ^ ((r) & 7))) << 4)))

__global__ void __launch_bounds__(256, 1) flash_attn_kernel(
    const bf* __restrict__ qkvh, const bf* __restrict__ qkvl,
    const bf* __restrict__ vth,  const bf* __restrict__ vtl,
    bf* __restrict__ oh, bf* __restrict__ ol)
{
    extern __shared__ char smem[];
    uint32_t sb = smem_to_u32(smem);
    const uint32_t QH = 0, QL = 16384, ST0 = 32768;

    int tid = threadIdx.x, wid = tid >> 5, lane = tid & 31;
    int z = blockIdx.y, b = z >> 3, hh = z & 7;
    int q0 = blockIdx.x * 128;

    const bf* gQh = qkvh + ((long)b * 2048 + q0) * 1536 + hh * 64;
    const bf* gQl = qkvl + ((long)b * 2048 + q0) * 1536 + hh * 64;
    const bf* gKh = qkvh + (long)b * 2048 * 1536 + 512 + hh * 64;
    const bf* gKl = qkvl + (long)b * 2048 * 1536 + 512 + hh * 64;
    const bf* gVh = vth + (long)z * 64 * 2048;
    const bf* gVl = vtl + (long)z * 64 * 2048;

    auto loadKV = [&](int j, int s) {
        uint32_t st = sb + ST0 + s * 65536;
#pragma unroll
        for (int i = tid; i < 1024; i += 256) {
            int r = i >> 3, c = i & 7;
            long go = (long)(j * 128 + r) * 1536 + c * 8;
            uint32_t so = ADDR8(r, c);
            CP_ASYNC16(st + so,         gKh + go);
            CP_ASYNC16(st + 16384 + so, gKl + go);
        }
#pragma unroll
        for (int i = tid; i < 1024; i += 256) {
            int r = i >> 4, c = i & 15;
            long go = (long)r * 2048 + j * 128 + c * 8;
            uint32_t so = ADDR16(r, c);
            CP_ASYNC16(st + 32768 + so, gVh + go);
            CP_ASYNC16(st + 49152 + so, gVl + go);
        }
    };

#pragma unroll
    for (int i = tid; i < 1024; i += 256) {
        int r = i >> 3, c = i & 7;
        long go = (long)r * 1536 + c * 8;
        uint32_t so = ADDR8(r, c);
        CP_ASYNC16(sb + QH + so, gQh + go);
        CP_ASYNC16(sb + QL + so, gQl + go);
    }
    loadKV(0, 0); CP_COMMIT();
    loadKV(1, 1); CP_COMMIT();

    int a_row = lane & 15, a_ch = lane >> 4;
    int b_row = ((lane >> 4) << 3) + (lane & 7), b_ch = (lane >> 3) & 1;

    uint32_t qh[4][4], ql[4][4];
    float accO[8][4];
#pragma unroll
    for (int i = 0; i < 8; i++)
#pragma unroll
        for (int e = 0; e < 4; e++) accO[i][e] = 0.f;
    float mrow[2] = {-1e30f, -1e30f}, lrow[2] = {0.f, 0.f};

    for (int j = 0; j < 16; j++) {
        if (j < 15) CP_WAIT1(); else CP_WAIT0();
        __syncthreads();
        if (j == 0) {
#pragma unroll
            for (int kk = 0; kk < 4; kk++) {
                uint32_t off = ADDR8(wid * 16 + a_row, 2 * kk + a_ch);
                ldm_x4(qh[kk], sb + QH + off);
                ldm_x4(ql[kk], sb + QL + off);
            }
        }
        uint32_t st = sb + ST0 + (j & 1) * 65536;

        float s[16][4];
#pragma unroll
        for (int i = 0; i < 16; i++)
#pragma unroll
            for (int e = 0; e < 4; e++) s[i][e] = 0.f;
#pragma unroll
        for (int kk = 0; kk < 4; kk++) {
#pragma unroll
            for (int ntp = 0; ntp < 8; ntp++) {
                uint32_t off = ADDR8(ntp * 16 + b_row, 2 * kk + b_ch);
                uint32_t bh[4], bl[4];
                ldm_x4(bh, st + off);
                ldm_x4(bl, st + 16384 + off);
                mma_bf16(s[2 * ntp],     qh[kk], bh + 0);
                mma_bf16(s[2 * ntp],     qh[kk], bl + 0);
                mma_bf16(s[2 * ntp],     ql[kk], bh + 0);
                mma_bf16(s[2 * ntp + 1], qh[kk], bh + 2);
                mma_bf16(s[2 * ntp + 1], qh[kk], bl + 2);
                mma_bf16(s[2 * ntp + 1], ql[kk], bh + 2);
            }
        }
#pragma unroll
        for (int i = 0; i < 16; i++)
#pragma unroll
            for (int e = 0; e < 4; e++) s[i][e] *= 0.125f;

#pragma unroll
        for (int h2 = 0; h2 < 2; h2++) {
            float vm = -1e30f;
#pragma unroll
            for (int nt = 0; nt < 16; nt++)
                vm = fmaxf(vm, fmaxf(s[nt][2 * h2], s[nt][2 * h2 + 1]));
            vm = fmaxf(vm, __shfl_xor_sync(0xffffffffu, vm, 1));
            vm = fmaxf(vm, __shfl_xor_sync(0xffffffffu, vm, 2));
            float mn = fmaxf(mrow[h2], vm);
            float scale = __expf(mrow[h2] - mn);
            mrow[h2] = mn;
            float ps = 0.f;
#pragma unroll
            for (int nt = 0; nt < 16; nt++) {
                float e0 = __expf(s[nt][2 * h2] - mn);
                float e1 = __expf(s[nt][2 * h2 + 1] - mn);
                s[nt][2 * h2] = e0; s[nt][2 * h2 + 1] = e1;
                ps += e0 + e1;
            }
            ps += __shfl_xor_sync(0xffffffffu, ps, 1);
            ps += __shfl_xor_sync(0xffffffffu, ps, 2);
            lrow[h2] = lrow[h2] * scale + ps;
#pragma unroll
            for (int nt2 = 0; nt2 < 8; nt2++) {
                accO[nt2][2 * h2]     *= scale;
                accO[nt2][2 * h2 + 1] *= scale;
            }
        }

#pragma unroll
        for (int kt = 0; kt < 8; kt++) {
            uint32_t Ph[4], Pl[4];
#pragma unroll
            for (int jj = 0; jj < 4; jj++) {
                float va = s[2 * kt + (jj >> 1)][(jj & 1) * 2];
                float vb = s[2 * kt + (jj >> 1)][(jj & 1) * 2 + 1];
                bf ha = __float2bfloat16(va), hb = __float2bfloat16(vb);
                float ra = va - __bfloat162float(ha), rb = vb - __bfloat162float(hb);
                Ph[jj] = (uint32_t)__bfloat16_as_ushort(ha) |
                         ((uint32_t)__bfloat16_as_ushort(hb) << 16);
                Pl[jj] = (uint32_t)__bfloat16_as_ushort(__float2bfloat16(ra)) |
                         ((uint32_t)__bfloat16_as_ushort(__float2bfloat16(rb)) << 16);
            }
#pragma unroll
            for (int np = 0; np < 4; np++) {
                uint32_t off = ADDR16(np * 16 + b_row, 2 * kt + b_ch);
                uint32_t vh[4], vl[4];
                ldm_x4(vh, st + 32768 + off);
                ldm_x4(vl, st + 49152 + off);
                mma_bf16(accO[2 * np],     Ph, vh + 0);
                mma_bf16(accO[2 * np],     Ph, vl + 0);
                mma_bf16(accO[2 * np],     Pl, vh + 0);
                mma_bf16(accO[2 * np + 1], Ph, vh + 2);
                mma_bf16(accO[2 * np + 1], Ph, vl + 2);
                mma_bf16(accO[2 * np + 1], Pl, vh + 2);
            }
        }
        __syncthreads();
        if (j + 2 < 16) { loadKV(j + 2, j & 1); CP_COMMIT(); }
    }

    float inv0 = 1.f / lrow[0], inv1 = 1.f / lrow[1];
    long tok0 = (long)b * 2048 + q0 + wid * 16 + (lane >> 2);
    int colb = hh * 64 + (lane & 3) * 2;
#pragma unroll
    for (int nt2 = 0; nt2 < 8; nt2++) {
#pragma unroll
        for (int e = 0; e < 4; e++) {
            long row = tok0 + 8 * (e >> 1);
            int col = colb + nt2 * 8 + (e & 1);
            float v = accO[nt2][e] * ((e >> 1) ? inv1 : inv0);
            bf h = __float2bfloat16(v);
            long off = row * 512 + col;
            oh[off] = h;
            ol[off] = __float2bfloat16(v - __bfloat162float(h));
        }
    }
}

// ===========================================================================
// Aux kernels
// ===========================================================================

// LayerNorm, one warp per row. grid = rows/8, block 256.
template <int D>
__global__ void ln_kernel(const float* __restrict__ x, const float* __restrict__ g,
                          const float* __restrict__ b, float* __restrict__ yf,
                          bf* __restrict__ yh, bf* __restrict__ yl, int ldy)
{
    constexpr int NP = D / 128;
    int wid = threadIdx.x >> 5, lane = threadIdx.x & 31;
    long row = (long)blockIdx.x * 8 + wid;
    const float* xr = x + row * D;

    float v[NP * 4];
    float s = 0.f;
#pragma unroll
    for (int p = 0; p < NP; p++) {
        float4 t = *(const float4*)(xr + p * 128 + lane * 4);
        v[4 * p] = t.x; v[4 * p + 1] = t.y; v[4 * p + 2] = t.z; v[4 * p + 3] = t.w;
        s += (t.x + t.y) + (t.z + t.w);
    }
#pragma unroll
    for (int o = 16; o; o >>= 1) s += __shfl_xor_sync(0xffffffffu, s, o);
    float mean = s * (1.f / D);
    float vs = 0.f;
#pragma unroll
    for (int i = 0; i < NP * 4; i++) { float d = v[i] - mean; vs += d * d; }
#pragma unroll
    for (int o = 16; o; o >>= 1) vs += __shfl_xor_sync(0xffffffffu, vs, o);
    float rstd = rsqrtf(vs * (1.f / D) + 1e-5f);

#pragma unroll
    for (int p = 0; p < NP; p++) {
        int idx = p * 128 + lane * 4;
        float4 gg = *(const float4*)(g + idx);
        float4 bb = *(const float4*)(b + idx);
        float o0 = (v[4 * p]     - mean) * rstd * gg.x + bb.x;
        float o1 = (v[4 * p + 1] - mean) * rstd * gg.y + bb.y;
        float o2 = (v[4 * p + 2] - mean) * rstd * gg.z + bb.z;
        float o3 = (v[4 * p + 3] - mean) * rstd * gg.w + bb.w;
        if (yf) {
            float4 t = {o0, o1, o2, o3};
            *(float4*)(yf + row * D + idx) = t;
        }
        if (yh) {
            long off = row * (long)ldy + idx;
            bf h0 = __float2bfloat16(o0), h1 = __float2bfloat16(o1);
            bf h2 = __float2bfloat16(o2), h3 = __float2bfloat16(o3);
            uint32_t hp0 = (uint32_t)__bfloat16_as_ushort(h0) |
                           ((uint32_t)__bfloat16_as_ushort(h1) << 16);
            uint32_t hp1 = (uint32_t)__bfloat16_as_ushort(h2) |
                           ((uint32_t)__bfloat16_as_ushort(h3) << 16);
            *(uint2*)(yh + off) = make_uint2(hp0, hp1);
            bf l0 = __float2bfloat16(o0 - __bfloat162float(h0));
            bf l1 = __float2bfloat16(o1 - __bfloat162float(h1));
            bf l2 = __float2bfloat16(o2 - __bfloat162float(h2));
            bf l3 = __float2bfloat16(o3 - __bfloat162float(h3));
            uint32_t lp0 = (uint32_t)__bfloat16_as_ushort(l0) |
                           ((uint32_t)__bfloat16_as_ushort(l1) << 16);
            uint32_t lp1 = (uint32_t)__bfloat16_as_ushort(l2) |
                           ((uint32_t)__bfloat16_as_ushort(l3) << 16);
            *(uint2*)(yl + off) = make_uint2(lp0, lp1);
        }
    }
}

// fp32 -> split bf16, 8 elems/thread, uint4 stores
__global__ void split_kernel(const float* __restrict__ x, bf* __restrict__ h,
                             bf* __restrict__ l, long n, int rowlen, int ldo)
{
    long i = ((long)blockIdx.x * 256 + threadIdx.x) * 8;
    if (i < n) {
        float4 v0 = *(const float4*)(x + i);
        float4 v1 = *(const float4*)(x + i + 4);
        float a[8] = {v0.x, v0.y, v0.z, v0.w, v1.x, v1.y, v1.z, v1.w};
        uint32_t hp[4], lp[4];
#pragma unroll
        for (int j = 0; j < 4; j++) {
            bf h0 = __float2bfloat16(a[2 * j]);
            bf h1 = __float2bfloat16(a[2 * j + 1]);
            hp[j] = (uint32_t)__bfloat16_as_ushort(h0) |
                    ((uint32_t)__bfloat16_as_ushort(h1) << 16);
            bf l0 = __float2bfloat16(a[2 * j] - __bfloat162float(h0));
            bf l1 = __float2bfloat16(a[2 * j + 1] - __bfloat162float(h1));
            lp[j] = (uint32_t)__bfloat16_as_ushort(l0) |
                    ((uint32_t)__bfloat16_as_ushort(l1) << 16);
        }
        long off = (i / rowlen) * (long)ldo + (i % rowlen);
        *(uint4*)(h + off) = make_uint4(hp[0], hp[1], hp[2], hp[3]);
        *(uint4*)(l + off) = make_uint4(lp[0], lp[1], lp[2], lp[3]);
    }
}

// All weight transposes + splits in ONE launch. W[K,N] fp32 -> Th/Tl [N,K] bf16.
struct WTDesc { const float* W; bf* Th; bf* Tl; int K; int N; int cum; };
struct WTArgs { WTDesc m[8]; };

__global__ void wtrans_all_kernel(WTArgs args)
{
    __shared__ float t[32][33];
    int bid = blockIdx.x;
    int mi = 0;
#pragma unroll
    for (int i = 0; i < 8; i++)
        if (bid >= args.m[i].cum) mi = i + 1;
    const WTDesc& d = args.m[mi];
    int local = bid - (mi ? args.m[mi - 1].cum : 0);
    int ktiles = d.K >> 5;
    int k0 = (local % ktiles) * 32, n0 = (local / ktiles) * 32;

    int x = threadIdx.x, y = threadIdx.y;   // 32 x 8
#pragma unroll
    for (int i = 0; i < 32; i += 8)
        t[y + i][x] = d.W[(long)(k0 + y + i) * d.N + n0 + x];
    __syncthreads();
#pragma unroll
    for (int i = 0; i < 32; i += 8) {
        float v = t[x][y + i];
        bf h = __float2bfloat16(v);
        long o = (long)(n0 + y + i) * d.K + k0 + x;
        d.Th[o] = h;
        d.Tl[o] = __float2bfloat16(v - __bfloat162float(h));
    }
}

// V transpose (bf16): qkv[:,1024+h*64 : +64] -> vt[z][64][2048]
__global__ void vtrans_kernel(const bf* __restrict__ qh, const bf* __restrict__ ql,
                              bf* __restrict__ vh, bf* __restrict__ vl)
{
    __shared__ bf th[32][33], tl[32][33];
    int z = blockIdx.z; int b = z >> 3, hh = z & 7;
    int k0 = blockIdx.x * 32, n0 = blockIdx.y * 32;
    int x = threadIdx.x, y = threadIdx.y;
    const long ibase = (long)b * 2048 * 1536 + 1024 + hh * 64;
#pragma unroll
    for (int i = 0; i < 32; i += 8) {
        long go = ibase + (long)(k0 + y + i) * 1536 + n0 + x;
        th[y + i][x] = qh[go];
        tl[y + i][x] = ql[go];
    }
    __syncthreads();
    const long obase = (long)z * 64 * 2048;
#pragma unroll
    for (int i = 0; i < 32; i += 8) {
        long o = obase + (long)(n0 + y + i) * 2048 + k0 + x;
        vh[o] = th[x][y + i];
        vl[o] = tl[x][y + i];
    }
}

// Pool phase 1: partial[z][b][h] = sum over s in [z*256,(z+1)*256)
__global__ void pool_partial_kernel(const float* __restrict__ hs, float* __restrict__ part)
{
    int b = blockIdx.y, z = blockIdx.z;
    int h = blockIdx.x * 256 + threadIdx.x;
    const float* p = hs + (long)b * SS * HH + (long)z * 256 * HH + h;
    float sum = 0.f;
#pragma unroll 8
    for (int s = 0; s < 256; s++) sum += p[(long)s * HH];
    part[((long)z * BB + b) * HH + h] = sum;
}

// Pool phase 2: pooled[b][h] = (sum of 8 partials) / 2048
__global__ void pool_reduce_kernel(const float* __restrict__ part, float* __restrict__ pooled)
{
    int b = blockIdx.y;
    int h = blockIdx.x * 256 + threadIdx.x;
    float sum = 0.f;
#pragma unroll
    for (int z = 0; z < 8; z++) sum += part[((long)z * BB + b) * HH + h];
    pooled[b * HH + h] = sum * (1.f / SS);
}

// CA layer 1, K-split partial GEMV: part[z][b][col] = pooled[b][z*128:+128] . w1-chunk
// grid (BB, 8), block 256 (one thread per output column); coalesced w1 loads.
__global__ void ca1_kernel(const float* __restrict__ pooled,
                           const float* __restrict__ w1, float* __restrict__ part)
{
    __shared__ float sp[128];
    int b = blockIdx.x, z = blockIdx.y;
    int t = threadIdx.x;
    if (t < 128) sp[t] = pooled[b * HH + z * 128 + t];
    __syncthreads();
    float acc = 0.f;
    const float* w = w1 + (long)z * 128 * 256 + t;
#pragma unroll 8
    for (int k = 0; k < 128; k++)
        acc = fmaf(sp[k], w[k * 256], acc);
    part[((long)z * BB + b) * 256 + t] = acc;
}

// CA: reduce layer-1 partials + bias + relu, then layers 2+3 (one block of 256)
__global__ void ca2_kernel(const float* __restrict__ part, const float* __restrict__ b1,
                           const float* __restrict__ w2, const float* __restrict__ b2,
                           const float* __restrict__ w3, const float* __restrict__ b3,
                           float* __restrict__ scores_out)
{
    __shared__ float h1[BB][256];
    __shared__ float h2[BB][32];
    int t = threadIdx.x;
#pragma unroll
    for (int b = 0; b < BB; b++) {
        float acc = b1[t];
#pragma unroll
        for (int z = 0; z < 8; z++) acc += part[((long)z * BB + b) * 256 + t];
        h1[b][t] = fmaxf(acc, 0.f);
    }
    __syncthreads();
    if (t < 32) {
        for (int b = 0; b < BB; b++) {
            float acc = b2[t];
            for (int k = 0; k < 256; k++)
                acc = fmaf(h1[b][k], w2[k * 32 + t], acc);
            h2[b][t] = fmaxf(acc, 0.f);
        }
    }
    __syncthreads();
    if (t < BB) {
        float acc = b3[0];
        for (int k = 0; k < 32; k++) acc = fmaf(h2[t][k], w3[k], acc);
        scores_out[t] = 1.f / (1.f + expf(-acc));
    }
}

// ===========================================================================
// Host
// ===========================================================================
static void launch_gemm(const bf* Ah, const bf* Al, const bf* Bh, const bf* Bl,
                        const float* bias, const float* res,
                        const float* f1, const float* f2,
                        float* C, bf* Ch, bf* Cl,
                        int M, int N, int K, int lda, int ldb, int ldc,
                        float alpha, int act)
{
    int sm = 2 * (2 * 128 * 64 + 2 * 128 * 64);   // 65536
    cudaFuncSetAttribute(gemm_tc_kernel, cudaFuncAttributeMaxDynamicSharedMemorySize, sm);
    dim3 grid(N / 128, M / 128, 1);
    gemm_tc_kernel<<<grid, 256, sm>>>(Ah, Al, Bh, Bl, bias, res, f1, f2, C, Ch, Cl,
        K, lda, ldb, ldc, alpha, act);
}

#define SYM(p, s) do { void* _t; cudaGetSymbolAddress(&_t, s); p = (decltype(p))_t; } while (0)

extern "C" void kernel_launch(void* const* d_in, const int* in_sizes, int n_in,
                              void* d_out, int out_size)
{
    const float* hs    = (const float*)d_in[0];
    const float* ca_w1 = (const float*)d_in[1];
    const float* ca_b1 = (const float*)d_in[2];
    const float* ca_w2 = (const float*)d_in[3];
    const float* ca_b2 = (const float*)d_in[4];
    const float* ca_w3 = (const float*)d_in[5];
    const float* ca_b3 = (const float*)d_in[6];
    const float* rp_w  = (const float*)d_in[7];
    const float* rp_b  = (const float*)d_in[8];
    const float* rn_g  = (const float*)d_in[9];
    const float* rn_b  = (const float*)d_in[10];
    const float* ln1_g = (const float*)d_in[11];
    const float* ln1_b = (const float*)d_in[12];
    const float* wqkv  = (const float*)d_in[13];
    const float* bqkv  = (const float*)d_in[14];
    const float* wo    = (const float*)d_in[15];
    const float* bo    = (const float*)d_in[16];
    const float* ln2_g = (const float*)d_in[17];
    const float* ln2_b = (const float*)d_in[18];
    const float* ff1_w = (const float*)d_in[19];
    const float* ff1_b = (const float*)d_in[20];
    const float* ff2_w = (const float*)d_in[21];
    const float* ff2_b = (const float*)d_in[22];
    const float* op_w  = (const float*)d_in[23];
    const float* op_b  = (const float*)d_in[24];
    const float* on_g  = (const float*)d_in[25];
    const float* on_b  = (const float*)d_in[26];
    const float* gw1   = (const float*)d_in[27];
    const float* gb1   = (const float*)d_in[28];
    const float* gw2   = (const float*)d_in[29];
    const float* gb2   = (const float*)d_in[30];

    float* out = (float*)d_out;
    float* cs  = out + NTOK * HH;

    float *poolp, *pooled, *h1p, *r, *tmpf, *reason;
    SYM(poolp, d_poolp); SYM(pooled, d_pooled); SYM(h1p, d_h1p);
    SYM(r, d_r); SYM(tmpf, d_tmpf); SYM(reason, d_reason);
    bf *cat_h, *cat_l, *y_h, *y_l, *qkv_h, *qkv_l, *vt_h, *vt_l;
    bf *o_h, *o_l, *ff_h, *ff_l, *rs_h, *rs_l, *t2_h, *t2_l;
    SYM(cat_h, d_cat_h); SYM(cat_l, d_cat_l); SYM(y_h, d_y_h); SYM(y_l, d_y_l);
    SYM(qkv_h, d_qkv_h); SYM(qkv_l, d_qkv_l);
    SYM(vt_h, d_vt_h); SYM(vt_l, d_vt_l);
    SYM(o_h, d_o_h); SYM(o_l, d_o_l); SYM(ff_h, d_ff_h); SYM(ff_l, d_ff_l);
    SYM(rs_h, d_rs_h); SYM(rs_l, d_rs_l);
    SYM(t2_h, d_t2_h); SYM(t2_l, d_t2_l);
    bf *rpT_h, *rpT_l, *qkvT_h, *qkvT_l, *woT_h, *woT_l, *ff1T_h, *ff1T_l;
    bf *ff2T_h, *ff2T_l, *opT_h, *opT_l, *g1T_h, *g1T_l, *g2T_h, *g2T_l;
    SYM(rpT_h, d_rpT_h); SYM(rpT_l, d_rpT_l); SYM(qkvT_h, d_qkvT_h); SYM(qkvT_l, d_qkvT_l);
    SYM(woT_h, d_woT_h); SYM(woT_l, d_woT_l); SYM(ff1T_h, d_ff1T_h); SYM(ff1T_l, d_ff1T_l);
    SYM(ff2T_h, d_ff2T_h); SYM(ff2T_l, d_ff2T_l); SYM(opT_h, d_opT_h); SYM(opT_l, d_opT_l);
    SYM(g1T_h, d_g1T_h); SYM(g1T_l, d_g1T_l); SYM(g2T_h, d_g2T_h); SYM(g2T_l, d_g2T_l);

    // -- all weight transposes + splits in one launch --
    {
        WTArgs wa;
        WTDesc ds[8] = {
            {rp_w,  rpT_h,  rpT_l,  1024, 512,  0},
            {wqkv,  qkvT_h, qkvT_l, 512,  1536, 0},
            {wo,    woT_h,  woT_l,  512,  512,  0},
            {ff1_w, ff1T_h, ff1T_l, 512,  2048, 0},
            {ff2_w, ff2T_h, ff2T_l, 2048, 512,  0},
            {op_w,  opT_h,  opT_l,  512,  1024, 0},
            {gw1,   g1T_h,  g1T_l,  2048, 1024, 0},
            {gw2,   g2T_h,  g2T_l,  1024, 1024, 0},
        };
        int cum = 0;
        for (int i = 0; i < 8; i++) {
            cum += (ds[i].K >> 5) * (ds[i].N >> 5);
            ds[i].cum = cum;
            wa.m[i] = ds[i];
        }
        wtrans_all_kernel<<<cum, dim3(32, 8)>>>(wa);
    }

    // -- complexity assessor (parallelized, K-split GEMV) --
    pool_partial_kernel<<<dim3(HH / 256, BB, 8), 256>>>(hs, poolp);
    pool_reduce_kernel<<<dim3(HH / 256, BB), 256>>>(poolp, pooled);
    ca1_kernel<<<dim3(BB, 8), 256>>>(pooled, ca_w1, h1p);
    ca2_kernel<<<1, 256>>>(h1p, ca_b1, ca_w2, ca_b2, ca_w3, ca_b3, cs);

    // -- split hidden states into cat[:, 0:1024] --
    split_kernel<<<(int)(NTOK * HH / 8 / 256), 256>>>(hs, cat_h, cat_l, NTOK * HH, 1024, 2048);

    // -- reasoning proj + pre-norm --
    launch_gemm(cat_h, cat_l, rpT_h, rpT_l, rp_b, nullptr, nullptr, nullptr,
                r, nullptr, nullptr, 8192, 512, 1024, 2048, 1024, 512, 1.f, 0);
    ln_kernel<512><<<1024, 256>>>(r, rn_g, rn_b, r, nullptr, nullptr, 512);

    // -- attention --
    ln_kernel<512><<<1024, 256>>>(r, ln1_g, ln1_b, nullptr, y_h, y_l, 512);
    launch_gemm(y_h, y_l, qkvT_h, qkvT_l, bqkv, nullptr, nullptr, nullptr,
                nullptr, qkv_h, qkv_l, 8192, 1536, 512, 512, 512, 1536, 1.f, 0);
    vtrans_kernel<<<dim3(64, 2, 32), dim3(32, 8)>>>(qkv_h, qkv_l, vt_h, vt_l);
    {
        cudaFuncSetAttribute(flash_attn_kernel,
                             cudaFuncAttributeMaxDynamicSharedMemorySize, 163840);
        dim3 grid(16, 32);
        flash_attn_kernel<<<grid, 256, 163840>>>(qkv_h, qkv_l, vt_h, vt_l, o_h, o_l);
    }
    // r = r + o @ wo + bo
    launch_gemm(o_h, o_l, woT_h, woT_l, bo, r, nullptr, nullptr,
                r, nullptr, nullptr, 8192, 512, 512, 512, 512, 512, 1.f, 0);

    // -- FFN --
    ln_kernel<512><<<1024, 256>>>(r, ln2_g, ln2_b, nullptr, y_h, y_l, 512);
    launch_gemm(y_h, y_l, ff1T_h, ff1T_l, ff1_b, nullptr, nullptr, nullptr,
                nullptr, ff_h, ff_l, 8192, 2048, 512, 512, 512, 2048, 1.f, 1);
    launch_gemm(ff_h, ff_l, ff2T_h, ff2T_l, ff2_b, r, nullptr, nullptr,
                r, nullptr, nullptr, 8192, 512, 2048, 2048, 2048, 512, 1.f, 0);

    // -- output projection + norm (reasoned also written into cat[:, 1024:2048]) --
    split_kernel<<<(int)(NTOK * RR / 8 / 256), 256>>>(r, rs_h, rs_l, NTOK * RR, 512, 512);
    launch_gemm(rs_h, rs_l, opT_h, opT_l, op_b, nullptr, nullptr, nullptr,
                tmpf, nullptr, nullptr, 8192, 1024, 512, 512, 512, 1024, 1.f, 0);
    ln_kernel<1024><<<1024, 256>>>(tmpf, on_g, on_b, reason, cat_h + 1024, cat_l + 1024, 2048);

    // -- integration gate: single K=2048 GEMM over [hs | reasoned], relu fused --
    launch_gemm(cat_h, cat_l, g1T_h, g1T_l, gb1, nullptr, nullptr, nullptr,
                nullptr, t2_h, t2_l, 8192, 1024, 2048, 2048, 2048, 1024, 1.f, 1);
    // g2 + sigmoid + final blend fused: out = hs + sigmoid(.)*reason
    launch_gemm(t2_h, t2_l, g2T_h, g2T_l, gb2, nullptr, hs, reason,
                out, nullptr, nullptr, 8192, 1024, 1024, 1024, 1024, 1024, 1.f, 3);
}

// round 17
// speedup vs baseline: 2.3019x; 1.0213x over previous
#include <cuda_runtime.h>
#include <cuda_bf16.h>
#include <cstdint>
#include <math.h>

typedef __nv_bfloat16 bf;

// Problem constants
#define BB 4
#define SS 2048
#define HH 1024
#define RR 512
#define NHEAD 8
#define HDIM 64
#define NTOK 8192L   // B*S

// ===========================================================================
// Baseline-PTX helpers (sm_80-era: ldmatrix / mma.sync / cp.async)
// ===========================================================================
__device__ __forceinline__ uint32_t smem_to_u32(const void* p) {
    uint32_t a;
    asm("{ .reg .u64 t; cvta.to.shared.u64 t, %1; cvt.u32.u64 %0, t; }" : "=r"(a) : "l"(p));
    return a;
}
__device__ __forceinline__ void ldm_x4(uint32_t* r, uint32_t addr) {
    asm volatile("ldmatrix.sync.aligned.m8n8.x4.shared.b16 {%0,%1,%2,%3}, [%4];"
                 : "=r"(r[0]), "=r"(r[1]), "=r"(r[2]), "=r"(r[3]) : "r"(addr));
}
__device__ __forceinline__ void mma_bf16(float* d, const uint32_t* a, const uint32_t* b) {
    asm volatile("mma.sync.aligned.m16n8k16.row.col.f32.bf16.bf16.f32 "
                 "{%0,%1,%2,%3}, {%4,%5,%6,%7}, {%8,%9}, {%0,%1,%2,%3};"
                 : "+f"(d[0]), "+f"(d[1]), "+f"(d[2]), "+f"(d[3])
                 : "r"(a[0]), "r"(a[1]), "r"(a[2]), "r"(a[3]), "r"(b[0]), "r"(b[1]));
}
#define CP_ASYNC16(dst, src) \
    asm volatile("cp.async.cg.shared.global [%0], [%1], 16;" :: "r"(dst), "l"(src))
#define CP_COMMIT() asm volatile("cp.async.commit_group;" ::: "memory")
#define CP_WAIT1()  asm volatile("cp.async.wait_group 1;" ::: "memory")
#define CP_WAIT0()  asm volatile("cp.async.wait_group 0;" ::: "memory")

// Swizzled smem offset: rows of 64B (32 bf16), 4x 16B chunks, XOR by (row>>1)&3
#define SWZ(row, c) ((uint32_t)((row) * 64 + (((c) ^ (((row) >> 1) & 3)) << 4)))

// ===========================================================================
// Scratch (static device globals; no allocation allowed)
// ===========================================================================
__device__ float d_poolp[8 * BB * HH];
__device__ float d_pooled[BB * HH];
__device__ float d_h1p[8 * BB * 256];
__device__ float d_r[NTOK * RR];
__device__ float d_tmpf[NTOK * HH];
__device__ float d_reason[NTOK * HH];

__device__ bf d_cat_h[NTOK * 2 * HH], d_cat_l[NTOK * 2 * HH];   // [hs | reasoned]
__device__ bf d_y_h[NTOK * RR],   d_y_l[NTOK * RR];
__device__ bf d_qkv_h[NTOK * 3 * RR], d_qkv_l[NTOK * 3 * RR];
__device__ bf d_vt_h[(long)BB * NHEAD * HDIM * SS], d_vt_l[(long)BB * NHEAD * HDIM * SS];
__device__ bf d_o_h[NTOK * RR],   d_o_l[NTOK * RR];
__device__ bf d_ff_h[NTOK * 4 * RR], d_ff_l[NTOK * 4 * RR];
__device__ bf d_rs_h[NTOK * RR],  d_rs_l[NTOK * RR];
__device__ bf d_t2_h[NTOK * HH],  d_t2_l[NTOK * HH];
// transposed + split weights ([N,K] bf16)
__device__ bf d_rpT_h[RR * HH],       d_rpT_l[RR * HH];
__device__ bf d_qkvT_h[3 * RR * RR],  d_qkvT_l[3 * RR * RR];
__device__ bf d_woT_h[RR * RR],       d_woT_l[RR * RR];
__device__ bf d_ff1T_h[4 * RR * RR],  d_ff1T_l[4 * RR * RR];
__device__ bf d_ff2T_h[RR * 4 * RR],  d_ff2T_l[RR * 4 * RR];
__device__ bf d_opT_h[HH * RR],       d_opT_l[HH * RR];
__device__ bf d_g1T_h[HH * 2 * HH],   d_g1T_l[HH * 2 * HH];
__device__ bf d_g2T_h[HH * HH],       d_g2T_l[HH * HH];

// ===========================================================================
// Warp-MMA split-bf16 GEMM (proven core): D = Ah*Bh + Ah*Bl + Al*Bh
//   CTA tile 128 x 128, BK=32, 8 warps (2m x 4n), 2-stage, 2 CTAs/SM.
//   act: 0 none, 1 relu, 2 sigmoid, 3 fused gate: C = f1 + sigmoid(v)*f2
// ===========================================================================
__global__ void __launch_bounds__(256, 2) gemm_tc_kernel(
    const bf* __restrict__ Ah, const bf* __restrict__ Al,
    const bf* __restrict__ Bh, const bf* __restrict__ Bl,
    const float* __restrict__ bias, const float* __restrict__ res,
    const float* __restrict__ f1, const float* __restrict__ f2,
    float* __restrict__ C, bf* __restrict__ Ch, bf* __restrict__ Cl,
    int K, int lda, int ldb, int ldc,
    float alpha, int act)
{
    constexpr int BN  = 128;
    constexpr int ATB = 128 * 64;
    constexpr int BTB = BN * 64;
    constexpr int STG = 2 * ATB + 2 * BTB;

    extern __shared__ char smem[];
    uint32_t sb = smem_to_u32(smem);

    int tid = threadIdx.x, wid = tid >> 5, lane = tid & 31;
    int wm = wid & 1, wn = wid >> 1;

    int m0 = blockIdx.y * 128, n0 = blockIdx.x * BN;
    const bf* gAh = Ah + (long)m0 * lda;
    const bf* gAl = Al + (long)m0 * lda;
    const bf* gBh = Bh + (long)n0 * ldb;
    const bf* gBl = Bl + (long)n0 * ldb;

    const int nc = K >> 5;

    auto load_chunk = [&](int c, int s) {
        uint32_t base = sb + s * STG;
        long ko = (long)c << 5;
#pragma unroll
        for (int i = tid; i < 512; i += 256) {
            int r = i >> 2, q = i & 3;
            long go = (long)r * lda + ko + q * 8;
            uint32_t so = SWZ(r, q);
            CP_ASYNC16(base + so,       gAh + go);
            CP_ASYNC16(base + ATB + so, gAl + go);
        }
#pragma unroll
        for (int i = tid; i < 512; i += 256) {
            int r = i >> 2, q = i & 3;
            long go = (long)r * ldb + ko + q * 8;
            uint32_t so = SWZ(r, q);
            CP_ASYNC16(base + 2 * ATB + so,       gBh + go);
            CP_ASYNC16(base + 2 * ATB + BTB + so, gBl + go);
        }
    };

    float acc[4][4][4];
#pragma unroll
    for (int i = 0; i < 4; i++)
#pragma unroll
        for (int j = 0; j < 4; j++)
#pragma unroll
            for (int k = 0; k < 4; k++) acc[i][j][k] = 0.f;

    int a_row = lane & 15, a_ch = lane >> 4;
    int b_row = ((lane >> 4) << 3) + (lane & 7), b_ch = (lane >> 3) & 1;

    load_chunk(0, 0); CP_COMMIT();
    if (nc > 1) { load_chunk(1, 1); CP_COMMIT(); }

    for (int c = 0; c < nc; c++) {
        int s = c & 1;
        if (c + 1 < nc) CP_WAIT1(); else CP_WAIT0();
        __syncthreads();

        uint32_t sAh_ = sb + s * STG;
        uint32_t sAl_ = sAh_ + ATB;
        uint32_t sBh_ = sAh_ + 2 * ATB;
        uint32_t sBl_ = sBh_ + BTB;

#pragma unroll
        for (int kk = 0; kk < 2; kk++) {
            uint32_t ah[4][4], al_[4][4];
#pragma unroll
            for (int mt = 0; mt < 4; mt++) {
                uint32_t off = SWZ(wm * 64 + mt * 16 + a_row, 2 * kk + a_ch);
                ldm_x4(ah[mt],  sAh_ + off);
                ldm_x4(al_[mt], sAl_ + off);
            }
#pragma unroll
            for (int ntp = 0; ntp < 2; ntp++) {
                uint32_t boff = SWZ(wn * 32 + ntp * 16 + b_row, 2 * kk + b_ch);
                uint32_t bh[4], bl[4];
                ldm_x4(bh, sBh_ + boff);
                ldm_x4(bl, sBl_ + boff);
#pragma unroll
                for (int mt = 0; mt < 4; mt++) {
                    mma_bf16(acc[mt][2 * ntp],     ah[mt],  bh + 0);
                    mma_bf16(acc[mt][2 * ntp],     ah[mt],  bl + 0);
                    mma_bf16(acc[mt][2 * ntp],     al_[mt], bh + 0);
                    mma_bf16(acc[mt][2 * ntp + 1], ah[mt],  bh + 2);
                    mma_bf16(acc[mt][2 * ntp + 1], ah[mt],  bl + 2);
                    mma_bf16(acc[mt][2 * ntp + 1], al_[mt], bh + 2);
                }
            }
        }
        __syncthreads();
        if (c + 2 < nc) { load_chunk(c + 2, s); CP_COMMIT(); }
    }

    // Epilogue
    int mrow = lane >> 2, nc2 = (lane & 3) * 2;
#pragma unroll
    for (int mt = 0; mt < 4; mt++) {
#pragma unroll
        for (int nt = 0; nt < 4; nt++) {
#pragma unroll
            for (int e = 0; e < 4; e++) {
                int gr = m0 + wm * 64 + mt * 16 + mrow + ((e >> 1) << 3);
                int gn = n0 + wn * 32 + nt * 8 + nc2 + (e & 1);
                float v = acc[mt][nt][e] * alpha;
                if (bias) v += bias[gn];
                long off = (long)gr * ldc + gn;
                if (res) v += res[off];
                if (act == 1)      v = fmaxf(v, 0.f);
                else if (act == 2) v = 1.f / (1.f + __expf(-v));
                else if (act == 3) { v = 1.f / (1.f + __expf(-v)); v = f1[off] + v * f2[off]; }
                if (C) C[off] = v;
                if (Ch) {
                    bf h = __float2bfloat16(v);
                    Ch[off] = h;
                    Cl[off] = __float2bfloat16(v - __bfloat162float(h));
                }
            }
        }
    }
}

// ===========================================================================
// FlashAttention-2 (unchanged, proven): per (b,h,128-query tile)
// ===========================================================================
#define ADDR8(r, c)  ((uint32_t)((r) * 128 + (((c) ^ ((r) & 7)) << 4)))
#define ADDR16(r, c) ((uint32_t)((r) * 256 + ((((c) & 8) | (((c) & 7) ^ ((r) & 7))) << 4)))

__global__ void __launch_bounds__(256, 1) flash_attn_kernel(
    const bf* __restrict__ qkvh, const bf* __restrict__ qkvl,
    const bf* __restrict__ vth,  const bf* __restrict__ vtl,
    bf* __restrict__ oh, bf* __restrict__ ol)
{
    extern __shared__ char smem[];
    uint32_t sb = smem_to_u32(smem);
    const uint32_t QH = 0, QL = 16384, ST0 = 32768;

    int tid = threadIdx.x, wid = tid >> 5, lane = tid & 31;
    int z = blockIdx.y, b = z >> 3, hh = z & 7;
    int q0 = blockIdx.x * 128;

    const bf* gQh = qkvh + ((long)b * 2048 + q0) * 1536 + hh * 64;
    const bf* gQl = qkvl + ((long)b * 2048 + q0) * 1536 + hh * 64;
    const bf* gKh = qkvh + (long)b * 2048 * 1536 + 512 + hh * 64;
    const bf* gKl = qkvl + (long)b * 2048 * 1536 + 512 + hh * 64;
    const bf* gVh = vth + (long)z * 64 * 2048;
    const bf* gVl = vtl + (long)z * 64 * 2048;

    auto loadKV = [&](int j, int s) {
        uint32_t st = sb + ST0 + s * 65536;
#pragma unroll
        for (int i = tid; i < 1024; i += 256) {
            int r = i >> 3, c = i & 7;
            long go = (long)(j * 128 + r) * 1536 + c * 8;
            uint32_t so = ADDR8(r, c);
            CP_ASYNC16(st + so,         gKh + go);
            CP_ASYNC16(st + 16384 + so, gKl + go);
        }
#pragma unroll
        for (int i = tid; i < 1024; i += 256) {
            int r = i >> 4, c = i & 15;
            long go = (long)r * 2048 + j * 128 + c * 8;
            uint32_t so = ADDR16(r, c);
            CP_ASYNC16(st + 32768 + so, gVh + go);
            CP_ASYNC16(st + 49152 + so, gVl + go);
        }
    };

#pragma unroll
    for (int i = tid; i < 1024; i += 256) {
        int r = i >> 3, c = i & 7;
        long go = (long)r * 1536 + c * 8;
        uint32_t so = ADDR8(r, c);
        CP_ASYNC16(sb + QH + so, gQh + go);
        CP_ASYNC16(sb + QL + so, gQl + go);
    }
    loadKV(0, 0); CP_COMMIT();
    loadKV(1, 1); CP_COMMIT();

    int a_row = lane & 15, a_ch = lane >> 4;
    int b_row = ((lane >> 4) << 3) + (lane & 7), b_ch = (lane >> 3) & 1;

    uint32_t qh[4][4], ql[4][4];
    float accO[8][4];
#pragma unroll
    for (int i = 0; i < 8; i++)
#pragma unroll
        for (int e = 0; e < 4; e++) accO[i][e] = 0.f;
    float mrow[2] = {-1e30f, -1e30f}, lrow[2] = {0.f, 0.f};

    for (int j = 0; j < 16; j++) {
        if (j < 15) CP_WAIT1(); else CP_WAIT0();
        __syncthreads();
        if (j == 0) {
#pragma unroll
            for (int kk = 0; kk < 4; kk++) {
                uint32_t off = ADDR8(wid * 16 + a_row, 2 * kk + a_ch);
                ldm_x4(qh[kk], sb + QH + off);
                ldm_x4(ql[kk], sb + QL + off);
            }
        }
        uint32_t st = sb + ST0 + (j & 1) * 65536;

        float s[16][4];
#pragma unroll
        for (int i = 0; i < 16; i++)
#pragma unroll
            for (int e = 0; e < 4; e++) s[i][e] = 0.f;
#pragma unroll
        for (int kk = 0; kk < 4; kk++) {
#pragma unroll
            for (int ntp = 0; ntp < 8; ntp++) {
                uint32_t off = ADDR8(ntp * 16 + b_row, 2 * kk + b_ch);
                uint32_t bh[4], bl[4];
                ldm_x4(bh, st + off);
                ldm_x4(bl, st + 16384 + off);
                mma_bf16(s[2 * ntp],     qh[kk], bh + 0);
                mma_bf16(s[2 * ntp],     qh[kk], bl + 0);
                mma_bf16(s[2 * ntp],     ql[kk], bh + 0);
                mma_bf16(s[2 * ntp + 1], qh[kk], bh + 2);
                mma_bf16(s[2 * ntp + 1], qh[kk], bl + 2);
                mma_bf16(s[2 * ntp + 1], ql[kk], bh + 2);
            }
        }
#pragma unroll
        for (int i = 0; i < 16; i++)
#pragma unroll
            for (int e = 0; e < 4; e++) s[i][e] *= 0.125f;

#pragma unroll
        for (int h2 = 0; h2 < 2; h2++) {
            float vm = -1e30f;
#pragma unroll
            for (int nt = 0; nt < 16; nt++)
                vm = fmaxf(vm, fmaxf(s[nt][2 * h2], s[nt][2 * h2 + 1]));
            vm = fmaxf(vm, __shfl_xor_sync(0xffffffffu, vm, 1));
            vm = fmaxf(vm, __shfl_xor_sync(0xffffffffu, vm, 2));
            float mn = fmaxf(mrow[h2], vm);
            float scale = __expf(mrow[h2] - mn);
            mrow[h2] = mn;
            float ps = 0.f;
#pragma unroll
            for (int nt = 0; nt < 16; nt++) {
                float e0 = __expf(s[nt][2 * h2] - mn);
                float e1 = __expf(s[nt][2 * h2 + 1] - mn);
                s[nt][2 * h2] = e0; s[nt][2 * h2 + 1] = e1;
                ps += e0 + e1;
            }
            ps += __shfl_xor_sync(0xffffffffu, ps, 1);
            ps += __shfl_xor_sync(0xffffffffu, ps, 2);
            lrow[h2] = lrow[h2] * scale + ps;
#pragma unroll
            for (int nt2 = 0; nt2 < 8; nt2++) {
                accO[nt2][2 * h2]     *= scale;
                accO[nt2][2 * h2 + 1] *= scale;
            }
        }

#pragma unroll
        for (int kt = 0; kt < 8; kt++) {
            uint32_t Ph[4], Pl[4];
#pragma unroll
            for (int jj = 0; jj < 4; jj++) {
                float va = s[2 * kt + (jj >> 1)][(jj & 1) * 2];
                float vb = s[2 * kt + (jj >> 1)][(jj & 1) * 2 + 1];
                bf ha = __float2bfloat16(va), hb = __float2bfloat16(vb);
                float ra = va - __bfloat162float(ha), rb = vb - __bfloat162float(hb);
                Ph[jj] = (uint32_t)__bfloat16_as_ushort(ha) |
                         ((uint32_t)__bfloat16_as_ushort(hb) << 16);
                Pl[jj] = (uint32_t)__bfloat16_as_ushort(__float2bfloat16(ra)) |
                         ((uint32_t)__bfloat16_as_ushort(__float2bfloat16(rb)) << 16);
            }
#pragma unroll
            for (int np = 0; np < 4; np++) {
                uint32_t off = ADDR16(np * 16 + b_row, 2 * kt + b_ch);
                uint32_t vh[4], vl[4];
                ldm_x4(vh, st + 32768 + off);
                ldm_x4(vl, st + 49152 + off);
                mma_bf16(accO[2 * np],     Ph, vh + 0);
                mma_bf16(accO[2 * np],     Ph, vl + 0);
                mma_bf16(accO[2 * np],     Pl, vh + 0);
                mma_bf16(accO[2 * np + 1], Ph, vh + 2);
                mma_bf16(accO[2 * np + 1], Ph, vl + 2);
                mma_bf16(accO[2 * np + 1], Pl, vh + 2);
            }
        }
        __syncthreads();
        if (j + 2 < 16) { loadKV(j + 2, j & 1); CP_COMMIT(); }
    }

    float inv0 = 1.f / lrow[0], inv1 = 1.f / lrow[1];
    long tok0 = (long)b * 2048 + q0 + wid * 16 + (lane >> 2);
    int colb = hh * 64 + (lane & 3) * 2;
#pragma unroll
    for (int nt2 = 0; nt2 < 8; nt2++) {
#pragma unroll
        for (int e = 0; e < 4; e++) {
            long row = tok0 + 8 * (e >> 1);
            int col = colb + nt2 * 8 + (e & 1);
            float v = accO[nt2][e] * ((e >> 1) ? inv1 : inv0);
            bf h = __float2bfloat16(v);
            long off = row * 512 + col;
            oh[off] = h;
            ol[off] = __float2bfloat16(v - __bfloat162float(h));
        }
    }
}

// ===========================================================================
// Aux kernels (unchanged from R16)
// ===========================================================================

// LayerNorm, one warp per row. grid = rows/8, block 256.
template <int D>
__global__ void ln_kernel(const float* __restrict__ x, const float* __restrict__ g,
                          const float* __restrict__ b, float* __restrict__ yf,
                          bf* __restrict__ yh, bf* __restrict__ yl, int ldy)
{
    constexpr int NP = D / 128;
    int wid = threadIdx.x >> 5, lane = threadIdx.x & 31;
    long row = (long)blockIdx.x * 8 + wid;
    const float* xr = x + row * D;

    float v[NP * 4];
    float s = 0.f;
#pragma unroll
    for (int p = 0; p < NP; p++) {
        float4 t = *(const float4*)(xr + p * 128 + lane * 4);
        v[4 * p] = t.x; v[4 * p + 1] = t.y; v[4 * p + 2] = t.z; v[4 * p + 3] = t.w;
        s += (t.x + t.y) + (t.z + t.w);
    }
#pragma unroll
    for (int o = 16; o; o >>= 1) s += __shfl_xor_sync(0xffffffffu, s, o);
    float mean = s * (1.f / D);
    float vs = 0.f;
#pragma unroll
    for (int i = 0; i < NP * 4; i++) { float d = v[i] - mean; vs += d * d; }
#pragma unroll
    for (int o = 16; o; o >>= 1) vs += __shfl_xor_sync(0xffffffffu, vs, o);
    float rstd = rsqrtf(vs * (1.f / D) + 1e-5f);

#pragma unroll
    for (int p = 0; p < NP; p++) {
        int idx = p * 128 + lane * 4;
        float4 gg = *(const float4*)(g + idx);
        float4 bb = *(const float4*)(b + idx);
        float o0 = (v[4 * p]     - mean) * rstd * gg.x + bb.x;
        float o1 = (v[4 * p + 1] - mean) * rstd * gg.y + bb.y;
        float o2 = (v[4 * p + 2] - mean) * rstd * gg.z + bb.z;
        float o3 = (v[4 * p + 3] - mean) * rstd * gg.w + bb.w;
        if (yf) {
            float4 t = {o0, o1, o2, o3};
            *(float4*)(yf + row * D + idx) = t;
        }
        if (yh) {
            long off = row * (long)ldy + idx;
            bf h0 = __float2bfloat16(o0), h1 = __float2bfloat16(o1);
            bf h2 = __float2bfloat16(o2), h3 = __float2bfloat16(o3);
            uint32_t hp0 = (uint32_t)__bfloat16_as_ushort(h0) |
                           ((uint32_t)__bfloat16_as_ushort(h1) << 16);
            uint32_t hp1 = (uint32_t)__bfloat16_as_ushort(h2) |
                           ((uint32_t)__bfloat16_as_ushort(h3) << 16);
            *(uint2*)(yh + off) = make_uint2(hp0, hp1);
            bf l0 = __float2bfloat16(o0 - __bfloat162float(h0));
            bf l1 = __float2bfloat16(o1 - __bfloat162float(h1));
            bf l2 = __float2bfloat16(o2 - __bfloat162float(h2));
            bf l3 = __float2bfloat16(o3 - __bfloat162float(h3));
            uint32_t lp0 = (uint32_t)__bfloat16_as_ushort(l0) |
                           ((uint32_t)__bfloat16_as_ushort(l1) << 16);
            uint32_t lp1 = (uint32_t)__bfloat16_as_ushort(l2) |
                           ((uint32_t)__bfloat16_as_ushort(l3) << 16);
            *(uint2*)(yl + off) = make_uint2(lp0, lp1);
        }
    }
}

// fp32 -> split bf16, 8 elems/thread, uint4 stores
__global__ void split_kernel(const float* __restrict__ x, bf* __restrict__ h,
                             bf* __restrict__ l, long n, int rowlen, int ldo)
{
    long i = ((long)blockIdx.x * 256 + threadIdx.x) * 8;
    if (i < n) {
        float4 v0 = *(const float4*)(x + i);
        float4 v1 = *(const float4*)(x + i + 4);
        float a[8] = {v0.x, v0.y, v0.z, v0.w, v1.x, v1.y, v1.z, v1.w};
        uint32_t hp[4], lp[4];
#pragma unroll
        for (int j = 0; j < 4; j++) {
            bf h0 = __float2bfloat16(a[2 * j]);
            bf h1 = __float2bfloat16(a[2 * j + 1]);
            hp[j] = (uint32_t)__bfloat16_as_ushort(h0) |
                    ((uint32_t)__bfloat16_as_ushort(h1) << 16);
            bf l0 = __float2bfloat16(a[2 * j] - __bfloat162float(h0));
            bf l1 = __float2bfloat16(a[2 * j + 1] - __bfloat162float(h1));
            lp[j] = (uint32_t)__bfloat16_as_ushort(l0) |
                    ((uint32_t)__bfloat16_as_ushort(l1) << 16);
        }
        long off = (i / rowlen) * (long)ldo + (i % rowlen);
        *(uint4*)(h + off) = make_uint4(hp[0], hp[1], hp[2], hp[3]);
        *(uint4*)(l + off) = make_uint4(lp[0], lp[1], lp[2], lp[3]);
    }
}

// All weight transposes + splits in ONE launch. W[K,N] fp32 -> Th/Tl [N,K] bf16.
struct WTDesc { const float* W; bf* Th; bf* Tl; int K; int N; int cum; };
struct WTArgs { WTDesc m[8]; };

__global__ void wtrans_all_kernel(WTArgs args)
{
    __shared__ float t[32][33];
    int bid = blockIdx.x;
    int mi = 0;
#pragma unroll
    for (int i = 0; i < 8; i++)
        if (bid >= args.m[i].cum) mi = i + 1;
    const WTDesc& d = args.m[mi];
    int local = bid - (mi ? args.m[mi - 1].cum : 0);
    int ktiles = d.K >> 5;
    int k0 = (local % ktiles) * 32, n0 = (local / ktiles) * 32;

    int x = threadIdx.x, y = threadIdx.y;   // 32 x 8
#pragma unroll
    for (int i = 0; i < 32; i += 8)
        t[y + i][x] = d.W[(long)(k0 + y + i) * d.N + n0 + x];
    __syncthreads();
#pragma unroll
    for (int i = 0; i < 32; i += 8) {
        float v = t[x][y + i];
        bf h = __float2bfloat16(v);
        long o = (long)(n0 + y + i) * d.K + k0 + x;
        d.Th[o] = h;
        d.Tl[o] = __float2bfloat16(v - __bfloat162float(h));
    }
}

// V transpose (bf16): qkv[:,1024+h*64 : +64] -> vt[z][64][2048]
__global__ void vtrans_kernel(const bf* __restrict__ qh, const bf* __restrict__ ql,
                              bf* __restrict__ vh, bf* __restrict__ vl)
{
    __shared__ bf th[32][33], tl[32][33];
    int z = blockIdx.z; int b = z >> 3, hh = z & 7;
    int k0 = blockIdx.x * 32, n0 = blockIdx.y * 32;
    int x = threadIdx.x, y = threadIdx.y;
    const long ibase = (long)b * 2048 * 1536 + 1024 + hh * 64;
#pragma unroll
    for (int i = 0; i < 32; i += 8) {
        long go = ibase + (long)(k0 + y + i) * 1536 + n0 + x;
        th[y + i][x] = qh[go];
        tl[y + i][x] = ql[go];
    }
    __syncthreads();
    const long obase = (long)z * 64 * 2048;
#pragma unroll
    for (int i = 0; i < 32; i += 8) {
        long o = obase + (long)(n0 + y + i) * 2048 + k0 + x;
        vh[o] = th[x][y + i];
        vl[o] = tl[x][y + i];
    }
}

// Pool phase 1: partial[z][b][h] = sum over s in [z*256,(z+1)*256)
__global__ void pool_partial_kernel(const float* __restrict__ hs, float* __restrict__ part)
{
    int b = blockIdx.y, z = blockIdx.z;
    int h = blockIdx.x * 256 + threadIdx.x;
    const float* p = hs + (long)b * SS * HH + (long)z * 256 * HH + h;
    float sum = 0.f;
#pragma unroll 8
    for (int s = 0; s < 256; s++) sum += p[(long)s * HH];
    part[((long)z * BB + b) * HH + h] = sum;
}

// Pool phase 2: pooled[b][h] = (sum of 8 partials) / 2048
__global__ void pool_reduce_kernel(const float* __restrict__ part, float* __restrict__ pooled)
{
    int b = blockIdx.y;
    int h = blockIdx.x * 256 + threadIdx.x;
    float sum = 0.f;
#pragma unroll
    for (int z = 0; z < 8; z++) sum += part[((long)z * BB + b) * HH + h];
    pooled[b * HH + h] = sum * (1.f / SS);
}

// CA layer 1, K-split partial GEMV
__global__ void ca1_kernel(const float* __restrict__ pooled,
                           const float* __restrict__ w1, float* __restrict__ part)
{
    __shared__ float sp[128];
    int b = blockIdx.x, z = blockIdx.y;
    int t = threadIdx.x;
    if (t < 128) sp[t] = pooled[b * HH + z * 128 + t];
    __syncthreads();
    float acc = 0.f;
    const float* w = w1 + (long)z * 128 * 256 + t;
#pragma unroll 8
    for (int k = 0; k < 128; k++)
        acc = fmaf(sp[k], w[k * 256], acc);
    part[((long)z * BB + b) * 256 + t] = acc;
}

// CA: reduce layer-1 partials + bias + relu, then layers 2+3
__global__ void ca2_kernel(const float* __restrict__ part, const float* __restrict__ b1,
                           const float* __restrict__ w2, const float* __restrict__ b2,
                           const float* __restrict__ w3, const float* __restrict__ b3,
                           float* __restrict__ scores_out)
{
    __shared__ float h1[BB][256];
    __shared__ float h2[BB][32];
    int t = threadIdx.x;
#pragma unroll
    for (int b = 0; b < BB; b++) {
        float acc = b1[t];
#pragma unroll
        for (int z = 0; z < 8; z++) acc += part[((long)z * BB + b) * 256 + t];
        h1[b][t] = fmaxf(acc, 0.f);
    }
    __syncthreads();
    if (t < 32) {
        for (int b = 0; b < BB; b++) {
            float acc = b2[t];
            for (int k = 0; k < 256; k++)
                acc = fmaf(h1[b][k], w2[k * 32 + t], acc);
            h2[b][t] = fmaxf(acc, 0.f);
        }
    }
    __syncthreads();
    if (t < BB) {
        float acc = b3[0];
        for (int k = 0; k < 32; k++) acc = fmaf(h2[t][k], w3[k], acc);
        scores_out[t] = 1.f / (1.f + expf(-acc));
    }
}

// ===========================================================================
// Host
// ===========================================================================
static void launch_gemm(const bf* Ah, const bf* Al, const bf* Bh, const bf* Bl,
                        const float* bias, const float* res,
                        const float* f1, const float* f2,
                        float* C, bf* Ch, bf* Cl,
                        int M, int N, int K, int lda, int ldb, int ldc,
                        float alpha, int act)
{
    int sm = 2 * (2 * 128 * 64 + 2 * 128 * 64);   // 65536
    cudaFuncSetAttribute(gemm_tc_kernel, cudaFuncAttributeMaxDynamicSharedMemorySize, sm);
    dim3 grid(N / 128, M / 128, 1);
    gemm_tc_kernel<<<grid, 256, sm>>>(Ah, Al, Bh, Bl, bias, res, f1, f2, C, Ch, Cl,
        K, lda, ldb, ldc, alpha, act);
}

#define SYM(p, s) do { void* _t; cudaGetSymbolAddress(&_t, s); p = (decltype(p))_t; } while (0)

extern "C" void kernel_launch(void* const* d_in, const int* in_sizes, int n_in,
                              void* d_out, int out_size)
{
    const float* hs    = (const float*)d_in[0];
    const float* ca_w1 = (const float*)d_in[1];
    const float* ca_b1 = (const float*)d_in[2];
    const float* ca_w2 = (const float*)d_in[3];
    const float* ca_b2 = (const float*)d_in[4];
    const float* ca_w3 = (const float*)d_in[5];
    const float* ca_b3 = (const float*)d_in[6];
    const float* rp_w  = (const float*)d_in[7];
    const float* rp_b  = (const float*)d_in[8];
    const float* rn_g  = (const float*)d_in[9];
    const float* rn_b  = (const float*)d_in[10];
    const float* ln1_g = (const float*)d_in[11];
    const float* ln1_b = (const float*)d_in[12];
    const float* wqkv  = (const float*)d_in[13];
    const float* bqkv  = (const float*)d_in[14];
    const float* wo    = (const float*)d_in[15];
    const float* bo    = (const float*)d_in[16];
    const float* ln2_g = (const float*)d_in[17];
    const float* ln2_b = (const float*)d_in[18];
    const float* ff1_w = (const float*)d_in[19];
    const float* ff1_b = (const float*)d_in[20];
    const float* ff2_w = (const float*)d_in[21];
    const float* ff2_b = (const float*)d_in[22];
    const float* op_w  = (const float*)d_in[23];
    const float* op_b  = (const float*)d_in[24];
    const float* on_g  = (const float*)d_in[25];
    const float* on_b  = (const float*)d_in[26];
    const float* gw1   = (const float*)d_in[27];
    const float* gb1   = (const float*)d_in[28];
    const float* gw2   = (const float*)d_in[29];
    const float* gb2   = (const float*)d_in[30];

    float* out = (float*)d_out;
    float* cs  = out + NTOK * HH;

    float *poolp, *pooled, *h1p, *r, *tmpf, *reason;
    SYM(poolp, d_poolp); SYM(pooled, d_pooled); SYM(h1p, d_h1p);
    SYM(r, d_r); SYM(tmpf, d_tmpf); SYM(reason, d_reason);
    bf *cat_h, *cat_l, *y_h, *y_l, *qkv_h, *qkv_l, *vt_h, *vt_l;
    bf *o_h, *o_l, *ff_h, *ff_l, *rs_h, *rs_l, *t2_h, *t2_l;
    SYM(cat_h, d_cat_h); SYM(cat_l, d_cat_l); SYM(y_h, d_y_h); SYM(y_l, d_y_l);
    SYM(qkv_h, d_qkv_h); SYM(qkv_l, d_qkv_l);
    SYM(vt_h, d_vt_h); SYM(vt_l, d_vt_l);
    SYM(o_h, d_o_h); SYM(o_l, d_o_l); SYM(ff_h, d_ff_h); SYM(ff_l, d_ff_l);
    SYM(rs_h, d_rs_h); SYM(rs_l, d_rs_l);
    SYM(t2_h, d_t2_h); SYM(t2_l, d_t2_l);
    bf *rpT_h, *rpT_l, *qkvT_h, *qkvT_l, *woT_h, *woT_l, *ff1T_h, *ff1T_l;
    bf *ff2T_h, *ff2T_l, *opT_h, *opT_l, *g1T_h, *g1T_l, *g2T_h, *g2T_l;
    SYM(rpT_h, d_rpT_h); SYM(rpT_l, d_rpT_l); SYM(qkvT_h, d_qkvT_h); SYM(qkvT_l, d_qkvT_l);
    SYM(woT_h, d_woT_h); SYM(woT_l, d_woT_l); SYM(ff1T_h, d_ff1T_h); SYM(ff1T_l, d_ff1T_l);
    SYM(ff2T_h, d_ff2T_h); SYM(ff2T_l, d_ff2T_l); SYM(opT_h, d_opT_h); SYM(opT_l, d_opT_l);
    SYM(g1T_h, d_g1T_h); SYM(g1T_l, d_g1T_l); SYM(g2T_h, d_g2T_h); SYM(g2T_l, d_g2T_l);

    // -- fork the (independent) complexity-assessor chain onto a side stream --
    cudaStream_t side;
    cudaEvent_t ev_fork, ev_join;
    cudaStreamCreateWithFlags(&side, cudaStreamNonBlocking);
    cudaEventCreateWithFlags(&ev_fork, cudaEventDisableTiming);
    cudaEventCreateWithFlags(&ev_join, cudaEventDisableTiming);
    cudaEventRecord(ev_fork, 0);
    cudaStreamWaitEvent(side, ev_fork, 0);

    pool_partial_kernel<<<dim3(HH / 256, BB, 8), 256, 0, side>>>(hs, poolp);
    pool_reduce_kernel<<<dim3(HH / 256, BB), 256, 0, side>>>(poolp, pooled);
    ca1_kernel<<<dim3(BB, 8), 256, 0, side>>>(pooled, ca_w1, h1p);
    ca2_kernel<<<1, 256, 0, side>>>(h1p, ca_b1, ca_w2, ca_b2, ca_w3, ca_b3, cs);
    cudaEventRecord(ev_join, side);

    // -- all weight transposes + splits in one launch (main stream) --
    {
        WTArgs wa;
        WTDesc ds[8] = {
            {rp_w,  rpT_h,  rpT_l,  1024, 512,  0},
            {wqkv,  qkvT_h, qkvT_l, 512,  1536, 0},
            {wo,    woT_h,  woT_l,  512,  512,  0},
            {ff1_w, ff1T_h, ff1T_l, 512,  2048, 0},
            {ff2_w, ff2T_h, ff2T_l, 2048, 512,  0},
            {op_w,  opT_h,  opT_l,  512,  1024, 0},
            {gw1,   g1T_h,  g1T_l,  2048, 1024, 0},
            {gw2,   g2T_h,  g2T_l,  1024, 1024, 0},
        };
        int cum = 0;
        for (int i = 0; i < 8; i++) {
            cum += (ds[i].K >> 5) * (ds[i].N >> 5);
            ds[i].cum = cum;
            wa.m[i] = ds[i];
        }
        wtrans_all_kernel<<<cum, dim3(32, 8)>>>(wa);
    }

    // -- split hidden states into cat[:, 0:1024] --
    split_kernel<<<(int)(NTOK * HH / 8 / 256), 256>>>(hs, cat_h, cat_l, NTOK * HH, 1024, 2048);

    // -- reasoning proj + pre-norm --
    launch_gemm(cat_h, cat_l, rpT_h, rpT_l, rp_b, nullptr, nullptr, nullptr,
                r, nullptr, nullptr, 8192, 512, 1024, 2048, 1024, 512, 1.f, 0);
    ln_kernel<512><<<1024, 256>>>(r, rn_g, rn_b, r, nullptr, nullptr, 512);

    // -- attention --
    ln_kernel<512><<<1024, 256>>>(r, ln1_g, ln1_b, nullptr, y_h, y_l, 512);
    launch_gemm(y_h, y_l, qkvT_h, qkvT_l, bqkv, nullptr, nullptr, nullptr,
                nullptr, qkv_h, qkv_l, 8192, 1536, 512, 512, 512, 1536, 1.f, 0);
    vtrans_kernel<<<dim3(64, 2, 32), dim3(32, 8)>>>(qkv_h, qkv_l, vt_h, vt_l);
    {
        cudaFuncSetAttribute(flash_attn_kernel,
                             cudaFuncAttributeMaxDynamicSharedMemorySize, 163840);
        dim3 grid(16, 32);
        flash_attn_kernel<<<grid, 256, 163840>>>(qkv_h, qkv_l, vt_h, vt_l, o_h, o_l);
    }
    // r = r + o @ wo + bo
    launch_gemm(o_h, o_l, woT_h, woT_l, bo, r, nullptr, nullptr,
                r, nullptr, nullptr, 8192, 512, 512, 512, 512, 512, 1.f, 0);

    // -- FFN --
    ln_kernel<512><<<1024, 256>>>(r, ln2_g, ln2_b, nullptr, y_h, y_l, 512);
    launch_gemm(y_h, y_l, ff1T_h, ff1T_l, ff1_b, nullptr, nullptr, nullptr,
                nullptr, ff_h, ff_l, 8192, 2048, 512, 512, 512, 2048, 1.f, 1);
    launch_gemm(ff_h, ff_l, ff2T_h, ff2T_l, ff2_b, r, nullptr, nullptr,
                r, nullptr, nullptr, 8192, 512, 2048, 2048, 2048, 512, 1.f, 0);

    // -- output projection + norm (reasoned also written into cat[:, 1024:2048]) --
    split_kernel<<<(int)(NTOK * RR / 8 / 256), 256>>>(r, rs_h, rs_l, NTOK * RR, 512, 512);
    launch_gemm(rs_h, rs_l, opT_h, opT_l, op_b, nullptr, nullptr, nullptr,
                tmpf, nullptr, nullptr, 8192, 1024, 512, 512, 512, 1024, 1.f, 0);
    ln_kernel<1024><<<1024, 256>>>(tmpf, on_g, on_b, reason, cat_h + 1024, cat_l + 1024, 2048);

    // -- integration gate: single K=2048 GEMM over [hs | reasoned], relu fused --
    launch_gemm(cat_h, cat_l, g1T_h, g1T_l, gb1, nullptr, nullptr, nullptr,
                nullptr, t2_h, t2_l, 8192, 1024, 2048, 2048, 2048, 1024, 1.f, 1);
    // g2 + sigmoid + final blend fused: out = hs + sigmoid(.)*reason
    launch_gemm(t2_h, t2_l, g2T_h, g2T_l, gb2, nullptr, hs, reason,
                out, nullptr, nullptr, 8192, 1024, 1024, 1024, 1024, 1024, 1.f, 3);

    // -- join the side stream before returning (graph end depends on CA chain) --
    cudaStreamWaitEvent(0, ev_join, 0);
}